// round 5
// baseline (speedup 1.0000x reference)
#include <cuda_runtime.h>
#include <cuda_bf16.h>
#include <cstdint>

using bf16 = __nv_bfloat16;
#define DI __device__ __forceinline__

static constexpr int BATCH = 16;
static constexpr int NPTS  = 2048;
static constexpr int ROWSZ = BATCH * NPTS;        // 32768
static constexpr int FEATD = 512;
static constexpr int KPAD0 = 576;                 // 9 chunks of 64
static constexpr int KPAD1 = 512;                 // 8 chunks

static constexpr size_t PLANE = (size_t)ROWSZ * FEATD * 2;  // one bf16 plane
static constexpr size_t TAILP = (size_t)ROWSZ * 64 * 2;
static constexpr size_t W0P   = (size_t)512 * KPAD0 * 2;
static constexpr size_t W1P   = (size_t)512 * KPAD1 * 2;

static constexpr size_t OFF_L   = 0;
static constexpr size_t OFF_H0  = 2 * PLANE;
static constexpr size_t OFF_H1  = 4 * PLANE;
static constexpr size_t OFF_T   = 6 * PLANE;
static constexpr size_t OFF_W0  = OFF_T + 6 * TAILP;
static constexpr size_t OFF_W1  = OFF_W0 + 6 * W0P;
static constexpr size_t OFF_ACC = OFF_W1 + 6 * W1P;
static constexpr size_t SCRATCH = OFF_ACC + (size_t)ROWSZ * 4;

__device__ __align__(128) char g_scratch[SCRATCH];

// ---------------------------------------------------------------- helpers
DI uint32_t s2u(const void* p) {
    uint32_t a;
    asm("{ .reg .u64 t; cvta.to.shared.u64 t, %1; cvt.u32.u64 %0, t; }"
        : "=r"(a) : "l"(p));
    return a;
}
DI void cpa16(uint32_t d, const void* s) {
    asm volatile("cp.async.cg.shared.global [%0], [%1], 16;" :: "r"(d), "l"(s));
}
DI void cpa_commit() { asm volatile("cp.async.commit_group;"); }
#define CPA_WAIT1() asm volatile("cp.async.wait_group 1;" ::: "memory")
#define CPA_WAIT0() asm volatile("cp.async.wait_group 0;" ::: "memory")

DI void ldm4(uint32_t* f, uint32_t a) {
    asm volatile("ldmatrix.sync.aligned.m8n8.x4.shared.b16 {%0,%1,%2,%3}, [%4];"
                 : "=r"(f[0]), "=r"(f[1]), "=r"(f[2]), "=r"(f[3]) : "r"(a));
}
DI void mma16816(float* d, const uint32_t* a, const uint32_t* b) {
    asm volatile(
        "mma.sync.aligned.m16n8k16.row.col.f32.bf16.bf16.f32 "
        "{%0,%1,%2,%3}, {%4,%5,%6,%7}, {%8,%9}, {%0,%1,%2,%3};"
        : "+f"(d[0]), "+f"(d[1]), "+f"(d[2]), "+f"(d[3])
        : "r"(a[0]), "r"(a[1]), "r"(a[2]), "r"(a[3]), "r"(b[0]), "r"(b[1]));
}

DI void split2(float x, bf16& h, bf16& l) {
    h = __float2bfloat16_rn(x);
    l = __float2bfloat16_rn(x - __bfloat162float(h));
}
DI uint32_t pack2(bf16 a, bf16 b) {
    __nv_bfloat162 t = __halves2bfloat162(a, b);
    return *reinterpret_cast<uint32_t*>(&t);
}
DI float dot3(float ax, float ay, float az, float bx, float by, float bz) {
    return fmaf(az, bz, fmaf(ay, by, ax * bx));
}

// ---------------------------------------------------------------- KNN + local cov
__global__ void knn_kernel(const float* __restrict__ pc, bf16* __restrict__ thi,
                           bf16* __restrict__ tlo) {
    __shared__ float sx[NPTS], sy[NPTS], sz[NPTS], sq[NPTS];
    int b = blockIdx.x >> 3, tile = blockIdx.x & 7;
    const float* p = pc + (size_t)b * NPTS * 3;
    for (int i = threadIdx.x; i < NPTS; i += 256) {
        float x = p[i * 3], y = p[i * 3 + 1], z = p[i * 3 + 2];
        sx[i] = x; sy[i] = y; sz[i] = z;
        sq[i] = dot3(x, y, z, x, y, z);
    }
    __syncthreads();
    int n = tile * 256 + threadIdx.x;
    float px = sx[n], py = sy[n], pz = sz[n], sn = sq[n];
    float v1 = -INFINITY, v2 = -INFINITY;
    int i1 = 0, i2 = 0;
    for (int m = 0; m < NPTS; m++) {
        float d = 2.f * dot3(px, py, pz, sx[m], sy[m], sz[m]) - sn - sq[m];
        if (d > v1) { v2 = v1; i2 = i1; v1 = d; i1 = m; }
        else if (d > v2) { v2 = d; i2 = m; }
    }
    float ax = sx[i1], ay = sy[i1], az = sz[i1];
    float bx = sx[i2], by = sy[i2], bz = sz[i2];
    float f[12] = { px, py, pz,
                    ax * bx, ax * by, ax * bz,
                    ay * bx, ay * by, ay * bz,
                    az * bx, az * by, az * bz };
    size_t row = (size_t)b * NPTS + n;
    for (int t = 0; t < 64; t++) {
        float v = (t < 12) ? f[t] : 0.f;
        bf16 h, l; split2(v, h, l);
        thi[row * 64 + t] = h;
        tlo[row * 64 + t] = l;
    }
}

// ---------------------------------------------------------------- fp32 -> hi/lo planes
__global__ void aconv_kernel(const float* __restrict__ X, bf16* __restrict__ hi,
                             bf16* __restrict__ lo) {
    size_t i = ((size_t)blockIdx.x * blockDim.x + threadIdx.x) * 4;
    float4 v = *reinterpret_cast<const float4*>(X + i);
    bf16 h0, l0, h1, l1, h2, l2, h3, l3;
    split2(v.x, h0, l0); split2(v.y, h1, l1);
    split2(v.z, h2, l2); split2(v.w, h3, l3);
    uint2 ho = make_uint2(pack2(h0, h1), pack2(h2, h3));
    uint2 lw = make_uint2(pack2(l0, l1), pack2(l2, l3));
    *reinterpret_cast<uint2*>(hi + i) = ho;
    *reinterpret_cast<uint2*>(lo + i) = lw;
}

// ---------------------------------------------------------------- weight transpose+split
__global__ void wconv_kernel(const float* __restrict__ W, bf16* __restrict__ Whi,
                             bf16* __restrict__ Wlo, int kdim, int kpad) {
    int idx = blockIdx.x * blockDim.x + threadIdx.x;
    if (idx >= 512 * kpad) return;
    int n = idx / kpad, k = idx - n * kpad;
    float v = (k < kdim) ? W[(size_t)k * 512 + n] : 0.f;
    bf16 h, l; split2(v, h, l);
    Whi[idx] = h;
    Wlo[idx] = l;
}

// ---------------------------------------------------------------- big GEMM (mma.sync)
// CTA 128x128, 8 warps (4M x 2N), warp tile 32x64, K-chunk 64, 2-stage cp.async.
static constexpr int PITCH   = 72;                  // halves per smem row (+8 pad)
static constexpr int TILE_B  = 128 * PITCH * 2;     // 18432 bytes, one plane
static constexpr int STAGE_B = 4 * TILE_B;          // Ahi,Alo,Bhi,Blo
static constexpr int GSMEM   = 2 * STAGE_B;         // 147456

__global__ __launch_bounds__(256, 1)
void gemm_kernel(const bf16* __restrict__ Ahi, const bf16* __restrict__ Alo,
                 const bf16* __restrict__ Thi, const bf16* __restrict__ Tlo,
                 const bf16* __restrict__ Bhi, const bf16* __restrict__ Blo,
                 const float* __restrict__ bias,
                 const bf16* __restrict__ Rhi, const bf16* __restrict__ Rlo,
                 bf16* __restrict__ Ohi, bf16* __restrict__ Olo,
                 int kpad, int nchunks) {
    extern __shared__ char sm[];

    const int tid  = threadIdx.x;
    const int lane = tid & 31, wid = tid >> 5;
    const int wM = wid >> 1, wN = wid & 1;          // 4 x 2 warp grid
    const int row0  = blockIdx.x * 128;
    const int ncol0 = blockIdx.y * 128;

    const uint32_t smem0 = s2u(sm);

    auto load_chunk = [&](int c, int st) {
        uint32_t base = smem0 + st * STAGE_B;
        #pragma unroll
        for (int it = 0; it < 4; it++) {
            int i = tid + it * 256;                 // 0..1023
            int r = i >> 3, j = i & 7;              // row 0..127, 16B slot 0..7
            uint32_t dst = base + r * (PITCH * 2) + j * 16;
            const bf16 *sa_h, *sa_l;
            if (c < 8) {
                sa_h = Ahi + (size_t)(row0 + r) * 512 + c * 64 + j * 8;
                sa_l = Alo + (size_t)(row0 + r) * 512 + c * 64 + j * 8;
            } else {
                sa_h = Thi + (size_t)(row0 + r) * 64 + j * 8;
                sa_l = Tlo + (size_t)(row0 + r) * 64 + j * 8;
            }
            cpa16(dst, sa_h);
            cpa16(dst + TILE_B, sa_l);
            const bf16* sb_h = Bhi + (size_t)(ncol0 + r) * kpad + c * 64 + j * 8;
            const bf16* sb_l = Blo + (size_t)(ncol0 + r) * kpad + c * 64 + j * 8;
            cpa16(dst + 2 * TILE_B, sb_h);
            cpa16(dst + 3 * TILE_B, sb_l);
        }
        cpa_commit();
    };

    float acc[2][8][4];
    #pragma unroll
    for (int a = 0; a < 2; a++)
        #pragma unroll
        for (int b = 0; b < 8; b++)
            #pragma unroll
            for (int k = 0; k < 4; k++) acc[a][b][k] = 0.f;

    // per-lane ldmatrix address offsets (halves)
    const int quad = lane >> 3, r8 = lane & 7;
    const int aRow = r8 + ((quad & 1) << 3), aCol = (quad >> 1) << 3;   // A tiles
    const int bRow = r8 + ((quad >> 1) << 3), bCol = (quad & 1) << 3;   // B tiles

    load_chunk(0, 0);
    if (nchunks > 1) load_chunk(1, 1);

    for (int c = 0; c < nchunks; c++) {
        int st = c & 1;
        if (c + 1 < nchunks) { CPA_WAIT1(); } else { CPA_WAIT0(); }
        __syncthreads();

        uint32_t base = smem0 + st * STAGE_B;
        #pragma unroll
        for (int ks = 0; ks < 4; ks++) {
            uint32_t ah[2][4], al[2][4];
            #pragma unroll
            for (int mt = 0; mt < 2; mt++) {
                uint32_t off =
                    ((wM * 32 + mt * 16 + aRow) * PITCH + ks * 16 + aCol) * 2;
                ldm4(ah[mt], base + off);
                ldm4(al[mt], base + TILE_B + off);
            }
            uint32_t bh[4][4], bl[4][4];
            #pragma unroll
            for (int ng = 0; ng < 4; ng++) {
                uint32_t off =
                    ((wN * 64 + ng * 16 + bRow) * PITCH + ks * 16 + bCol) * 2;
                ldm4(bh[ng], base + 2 * TILE_B + off);
                ldm4(bl[ng], base + 3 * TILE_B + off);
            }
            #pragma unroll
            for (int mt = 0; mt < 2; mt++)
                #pragma unroll
                for (int nt = 0; nt < 8; nt++) {
                    const uint32_t* Bh = &bh[nt >> 1][(nt & 1) * 2];
                    const uint32_t* Bl = &bl[nt >> 1][(nt & 1) * 2];
                    mma16816(acc[mt][nt], ah[mt], Bh);   // hi*hi
                    mma16816(acc[mt][nt], al[mt], Bh);   // lo*hi
                    mma16816(acc[mt][nt], ah[mt], Bl);   // hi*lo
                }
        }
        __syncthreads();
        if (c + 2 < nchunks) load_chunk(c + 2, st);
    }

    // epilogue: bias (+residual) + relu + split + store
    const int gid = lane >> 2, tig = lane & 3;
    #pragma unroll
    for (int mt = 0; mt < 2; mt++) {
        int rg0 = row0 + wM * 32 + mt * 16 + gid;
        #pragma unroll
        for (int nt = 0; nt < 8; nt++) {
            int col = ncol0 + wN * 64 + nt * 8 + tig * 2;
            float b0 = __ldg(&bias[col]), b1 = __ldg(&bias[col + 1]);
            #pragma unroll
            for (int half = 0; half < 2; half++) {
                int row = rg0 + half * 8;
                float v0 = acc[mt][nt][half * 2]     + b0;
                float v1 = acc[mt][nt][half * 2 + 1] + b1;
                if (Rhi) {
                    uint32_t hw = *(const uint32_t*)(Rhi + (size_t)row * 512 + col);
                    uint32_t lw = *(const uint32_t*)(Rlo + (size_t)row * 512 + col);
                    __nv_bfloat162 hh = *reinterpret_cast<__nv_bfloat162*>(&hw);
                    __nv_bfloat162 ll = *reinterpret_cast<__nv_bfloat162*>(&lw);
                    v0 += __low2float(hh) + __low2float(ll);
                    v1 += __high2float(hh) + __high2float(ll);
                }
                v0 = fmaxf(v0, 0.f);
                v1 = fmaxf(v1, 0.f);
                bf16 h0, l0, h1, l1;
                split2(v0, h0, l0);
                split2(v1, h1, l1);
                *(uint32_t*)(Ohi + (size_t)row * 512 + col) = pack2(h0, h1);
                *(uint32_t*)(Olo + (size_t)row * 512 + col) = pack2(l0, l1);
            }
        }
    }
}

// ---------------------------------------------------------------- GEMV (last layer) + chain
__global__ void gemv_kernel(const bf16* __restrict__ Hhi, const bf16* __restrict__ Hlo,
                            const float* __restrict__ W2, const float* __restrict__ b2,
                            const float* __restrict__ prev, float* __restrict__ acc,
                            bf16* __restrict__ thi, bf16* __restrict__ tlo,
                            float* __restrict__ fout) {
    int warp = threadIdx.x >> 5, lane = threadIdx.x & 31;
    size_t row = (size_t)blockIdx.x * 8 + warp;
    const bf16* ph = Hhi + row * 512;
    const bf16* pl = Hlo + row * 512;
    float s = 0.f;
    #pragma unroll
    for (int t = 0; t < 16; t++) {
        int col = t * 32 + lane;
        float hv = __bfloat162float(ph[col]) + __bfloat162float(pl[col]);
        s = fmaf(hv, __ldg(&W2[col]), s);
    }
    #pragma unroll
    for (int o = 16; o; o >>= 1) s += __shfl_xor_sync(0xffffffffu, s, o);
    float g = s + __ldg(&b2[0]);
    float ov = (prev ? prev[row] : 0.f) + g;
    if (fout) {
        if (lane == 0) fout[row] = ov;
    } else {
        if (lane == 0) acc[row] = ov;
        bf16 h, l; split2(ov, h, l);
        thi[row * 64 + lane] = (lane == 0) ? h : __float2bfloat16_rn(0.f);
        tlo[row * 64 + lane] = (lane == 0) ? l : __float2bfloat16_rn(0.f);
        thi[row * 64 + lane + 32] = __float2bfloat16_rn(0.f);
        tlo[row * 64 + lane + 32] = __float2bfloat16_rn(0.f);
    }
}

// ---------------------------------------------------------------- launch
extern "C" void kernel_launch(void* const* d_in, const int* in_sizes, int n_in,
                              void* d_out, int out_size) {
    const float* latent = (const float*)d_in[0];
    const float* pc     = (const float*)d_in[1];
    const float* W[3][3];
    const float* Bv[3][3];
    int p = 2;
    for (int s = 0; s < 3; s++)
        for (int j = 0; j < 3; j++) { W[s][j] = (const float*)d_in[p++]; Bv[s][j] = (const float*)d_in[p++]; }

    char* S = nullptr;
    cudaGetSymbolAddress((void**)&S, g_scratch);
    bf16* Lhi  = (bf16*)(S + OFF_L);
    bf16* Llo  = (bf16*)(S + OFF_L + PLANE);
    bf16* h0hi = (bf16*)(S + OFF_H0);
    bf16* h0lo = (bf16*)(S + OFF_H0 + PLANE);
    bf16* h1hi = (bf16*)(S + OFF_H1);
    bf16* h1lo = (bf16*)(S + OFF_H1 + PLANE);
    bf16* thi[3], *tlo[3];
    for (int s = 0; s < 3; s++) {
        thi[s] = (bf16*)(S + OFF_T + (2 * s) * TAILP);
        tlo[s] = (bf16*)(S + OFF_T + (2 * s + 1) * TAILP);
    }
    bf16* w0hi[3], *w0lo[3], *w1hi[3], *w1lo[3];
    for (int s = 0; s < 3; s++) {
        w0hi[s] = (bf16*)(S + OFF_W0 + (2 * s) * W0P);
        w0lo[s] = (bf16*)(S + OFF_W0 + (2 * s + 1) * W0P);
        w1hi[s] = (bf16*)(S + OFF_W1 + (2 * s) * W1P);
        w1lo[s] = (bf16*)(S + OFF_W1 + (2 * s + 1) * W1P);
    }
    float* acc = (float*)(S + OFF_ACC);

    cudaFuncSetAttribute(gemm_kernel, cudaFuncAttributeMaxDynamicSharedMemorySize, GSMEM);

    knn_kernel<<<BATCH * 8, 256>>>(pc, thi[0], tlo[0]);
    aconv_kernel<<<(ROWSZ * FEATD / 4) / 256, 256>>>(latent, Lhi, Llo);
    int kdim0[3] = {FEATD + 12, FEATD + 1, FEATD + 1};
    for (int s = 0; s < 3; s++) {
        wconv_kernel<<<(512 * KPAD0 + 255) / 256, 256>>>(W[s][0], w0hi[s], w0lo[s], kdim0[s], KPAD0);
        wconv_kernel<<<(512 * KPAD1 + 255) / 256, 256>>>(W[s][1], w1hi[s], w1lo[s], 512, KPAD1);
    }

    dim3 ggrid(ROWSZ / 128, 512 / 128);
    for (int s = 0; s < 3; s++) {
        gemm_kernel<<<ggrid, 256, GSMEM>>>(Lhi, Llo, thi[s], tlo[s],
                                           w0hi[s], w0lo[s], Bv[s][0],
                                           nullptr, nullptr, h0hi, h0lo, KPAD0, 9);
        gemm_kernel<<<ggrid, 256, GSMEM>>>(h0hi, h0lo, nullptr, nullptr,
                                           w1hi[s], w1lo[s], Bv[s][1],
                                           h0hi, h0lo, h1hi, h1lo, KPAD1, 8);
        const float* prev = (s == 0) ? nullptr : acc;
        if (s < 2)
            gemv_kernel<<<ROWSZ / 8, 256>>>(h1hi, h1lo, W[s][2], Bv[s][2],
                                            prev, acc, thi[s + 1], tlo[s + 1], nullptr);
        else
            gemv_kernel<<<ROWSZ / 8, 256>>>(h1hi, h1lo, W[s][2], Bv[s][2],
                                            prev, acc, nullptr, nullptr, (float*)d_out);
    }
}

// round 6
// speedup vs baseline: 1.0338x; 1.0338x over previous
#include <cuda_runtime.h>
#include <cuda_bf16.h>
#include <cstdint>

using bf16 = __nv_bfloat16;
#define DI __device__ __forceinline__

static constexpr int BATCH = 16;
static constexpr int NPTS  = 2048;
static constexpr int ROWSZ = BATCH * NPTS;        // 32768
static constexpr int FEATD = 512;
static constexpr int KPAD0 = 576;                 // 9 chunks of 64
static constexpr int KPAD1 = 512;                 // 8 chunks

static constexpr size_t PLANE = (size_t)ROWSZ * FEATD * 2;  // one bf16 plane
static constexpr size_t TAILP = (size_t)ROWSZ * 64 * 2;
static constexpr size_t W0P   = (size_t)512 * KPAD0 * 2;
static constexpr size_t W1P   = (size_t)512 * KPAD1 * 2;

static constexpr size_t OFF_L    = 0;
static constexpr size_t OFF_H0   = 2 * PLANE;
static constexpr size_t OFF_ACC8 = 4 * PLANE;                 // 32768*8 floats = 1MB
static constexpr size_t OFF_T    = OFF_ACC8 + (size_t)ROWSZ * 8 * 4;
static constexpr size_t OFF_W0   = OFF_T + 6 * TAILP;
static constexpr size_t OFF_W1   = OFF_W0 + 6 * W0P;
static constexpr size_t OFF_ACC  = OFF_W1 + 6 * W1P;
static constexpr size_t SCRATCH  = OFF_ACC + (size_t)ROWSZ * 4;

__device__ __align__(128) char g_scratch[SCRATCH];

// ---------------------------------------------------------------- helpers
DI uint32_t s2u(const void* p) {
    uint32_t a;
    asm("{ .reg .u64 t; cvta.to.shared.u64 t, %1; cvt.u32.u64 %0, t; }"
        : "=r"(a) : "l"(p));
    return a;
}
DI void cpa16(uint32_t d, const void* s) {
    asm volatile("cp.async.cg.shared.global [%0], [%1], 16;" :: "r"(d), "l"(s));
}
DI void cpa_commit() { asm volatile("cp.async.commit_group;"); }
#define CPA_WAIT1() asm volatile("cp.async.wait_group 1;" ::: "memory")
#define CPA_WAIT0() asm volatile("cp.async.wait_group 0;" ::: "memory")

DI void ldm4(uint32_t* f, uint32_t a) {
    asm volatile("ldmatrix.sync.aligned.m8n8.x4.shared.b16 {%0,%1,%2,%3}, [%4];"
                 : "=r"(f[0]), "=r"(f[1]), "=r"(f[2]), "=r"(f[3]) : "r"(a));
}
DI void mma16816(float* d, const uint32_t* a, const uint32_t* b) {
    asm volatile(
        "mma.sync.aligned.m16n8k16.row.col.f32.bf16.bf16.f32 "
        "{%0,%1,%2,%3}, {%4,%5,%6,%7}, {%8,%9}, {%0,%1,%2,%3};"
        : "+f"(d[0]), "+f"(d[1]), "+f"(d[2]), "+f"(d[3])
        : "r"(a[0]), "r"(a[1]), "r"(a[2]), "r"(a[3]), "r"(b[0]), "r"(b[1]));
}

DI void split2(float x, bf16& h, bf16& l) {
    h = __float2bfloat16_rn(x);
    l = __float2bfloat16_rn(x - __bfloat162float(h));
}
DI uint32_t pack2(bf16 a, bf16 b) {
    __nv_bfloat162 t = __halves2bfloat162(a, b);
    return *reinterpret_cast<uint32_t*>(&t);
}
DI float dot3(float ax, float ay, float az, float bx, float by, float bz) {
    return fmaf(az, bz, fmaf(ay, by, ax * bx));
}

// ---------------------------------------------------------------- KNN + local cov
__global__ void knn_kernel(const float* __restrict__ pc, bf16* __restrict__ thi,
                           bf16* __restrict__ tlo) {
    __shared__ float sx[NPTS], sy[NPTS], sz[NPTS], sq[NPTS];
    int b = blockIdx.x >> 3, tile = blockIdx.x & 7;
    const float* p = pc + (size_t)b * NPTS * 3;
    for (int i = threadIdx.x; i < NPTS; i += 256) {
        float x = p[i * 3], y = p[i * 3 + 1], z = p[i * 3 + 2];
        sx[i] = x; sy[i] = y; sz[i] = z;
        sq[i] = dot3(x, y, z, x, y, z);
    }
    __syncthreads();
    int n = tile * 256 + threadIdx.x;
    float px = sx[n], py = sy[n], pz = sz[n], sn = sq[n];
    float v1 = -INFINITY, v2 = -INFINITY;
    int i1 = 0, i2 = 0;
    for (int m = 0; m < NPTS; m++) {
        float d = 2.f * dot3(px, py, pz, sx[m], sy[m], sz[m]) - sn - sq[m];
        if (d > v1) { v2 = v1; i2 = i1; v1 = d; i1 = m; }
        else if (d > v2) { v2 = d; i2 = m; }
    }
    float ax = sx[i1], ay = sy[i1], az = sz[i1];
    float bx = sx[i2], by = sy[i2], bz = sz[i2];
    float f[12] = { px, py, pz,
                    ax * bx, ax * by, ax * bz,
                    ay * bx, ay * by, ay * bz,
                    az * bx, az * by, az * bz };
    size_t row = (size_t)b * NPTS + n;
    for (int t = 0; t < 64; t++) {
        float v = (t < 12) ? f[t] : 0.f;
        bf16 h, l; split2(v, h, l);
        thi[row * 64 + t] = h;
        tlo[row * 64 + t] = l;
    }
}

// ---------------------------------------------------------------- fp32 -> hi/lo planes
__global__ void aconv_kernel(const float* __restrict__ X, bf16* __restrict__ hi,
                             bf16* __restrict__ lo) {
    size_t i = ((size_t)blockIdx.x * blockDim.x + threadIdx.x) * 4;
    float4 v = *reinterpret_cast<const float4*>(X + i);
    bf16 h0, l0, h1, l1, h2, l2, h3, l3;
    split2(v.x, h0, l0); split2(v.y, h1, l1);
    split2(v.z, h2, l2); split2(v.w, h3, l3);
    uint2 ho = make_uint2(pack2(h0, h1), pack2(h2, h3));
    uint2 lw = make_uint2(pack2(l0, l1), pack2(l2, l3));
    *reinterpret_cast<uint2*>(hi + i) = ho;
    *reinterpret_cast<uint2*>(lo + i) = lw;
}

// ---------------------------------------------------------------- weight transpose+split
__global__ void wconv_kernel(const float* __restrict__ W, bf16* __restrict__ Whi,
                             bf16* __restrict__ Wlo, int kdim, int kpad) {
    int idx = blockIdx.x * blockDim.x + threadIdx.x;
    if (idx >= 512 * kpad) return;
    int n = idx / kpad, k = idx - n * kpad;
    float v = (k < kdim) ? W[(size_t)k * 512 + n] : 0.f;
    bf16 h, l; split2(v, h, l);
    Whi[idx] = h;
    Wlo[idx] = l;
}

// ---------------------------------------------------------------- big GEMM (mma.sync)
// CTA 256x128, 16 warps (8M x 2N), warp tile 32x64, K-chunk 64, 2-stage cp.async.
static constexpr int PITCH   = 72;                     // halves per smem row (+8 pad)
static constexpr int TILE_A  = 256 * PITCH * 2;        // 36864 B per A plane
static constexpr int TILE_W  = 128 * PITCH * 2;        // 18432 B per B plane
static constexpr int STAGE_B = 2 * TILE_A + 2 * TILE_W;// 110592
static constexpr int GSMEM   = 2 * STAGE_B;            // 221184

__global__ __launch_bounds__(512, 1)
void gemm_kernel(const bf16* __restrict__ Ahi, const bf16* __restrict__ Alo,
                 const bf16* __restrict__ Thi, const bf16* __restrict__ Tlo,
                 const bf16* __restrict__ Bhi, const bf16* __restrict__ Blo,
                 const float* __restrict__ bias,
                 const bf16* __restrict__ Rhi, const bf16* __restrict__ Rlo,
                 bf16* __restrict__ Ohi, bf16* __restrict__ Olo,
                 const float* __restrict__ Wv, float* __restrict__ acc8,
                 int kpad, int nchunks) {
    extern __shared__ char sm[];

    const int tid  = threadIdx.x;
    const int lane = tid & 31, wid = tid >> 5;
    const int wM = wid >> 1, wN = wid & 1;             // 8 x 2 warp grid
    const int row0  = blockIdx.x * 256;
    const int ncol0 = blockIdx.y * 128;

    const uint32_t smem0 = s2u(sm);

    auto load_chunk = [&](int c, int st) {
        uint32_t base = smem0 + st * STAGE_B;
        #pragma unroll
        for (int it = 0; it < 4; it++) {
            int i = tid + it * 512;                    // 0..2047
            int r = i >> 3, j = i & 7;                 // row 0..255, slot 0..7
            uint32_t dst = base + r * (PITCH * 2) + j * 16;
            const bf16 *ph, *pl;
            if (c < 8) {
                ph = Ahi + (size_t)(row0 + r) * 512 + c * 64 + j * 8;
                pl = Alo + (size_t)(row0 + r) * 512 + c * 64 + j * 8;
            } else {
                ph = Thi + (size_t)(row0 + r) * 64 + j * 8;
                pl = Tlo + (size_t)(row0 + r) * 64 + j * 8;
            }
            cpa16(dst, ph);
            cpa16(dst + TILE_A, pl);
        }
        #pragma unroll
        for (int it = 0; it < 2; it++) {
            int i = tid + it * 512;                    // 0..1023
            int r = i >> 3, j = i & 7;                 // row 0..127
            uint32_t dst = base + 2 * TILE_A + r * (PITCH * 2) + j * 16;
            cpa16(dst,          Bhi + (size_t)(ncol0 + r) * kpad + c * 64 + j * 8);
            cpa16(dst + TILE_W, Blo + (size_t)(ncol0 + r) * kpad + c * 64 + j * 8);
        }
        cpa_commit();
    };

    float acc[2][8][4];
    #pragma unroll
    for (int a = 0; a < 2; a++)
        #pragma unroll
        for (int b = 0; b < 8; b++)
            #pragma unroll
            for (int k = 0; k < 4; k++) acc[a][b][k] = 0.f;

    const int quad = lane >> 3, r8 = lane & 7;
    const int aRow = r8 + ((quad & 1) << 3), aCol = (quad >> 1) << 3;
    const int bRow = r8 + ((quad >> 1) << 3), bCol = (quad & 1) << 3;

    load_chunk(0, 0);
    if (nchunks > 1) load_chunk(1, 1);

    for (int c = 0; c < nchunks; c++) {
        int st = c & 1;
        if (c + 1 < nchunks) { CPA_WAIT1(); } else { CPA_WAIT0(); }
        __syncthreads();

        uint32_t base = smem0 + st * STAGE_B;
        #pragma unroll
        for (int ks = 0; ks < 4; ks++) {
            uint32_t ah[2][4], al[2][4];
            #pragma unroll
            for (int mt = 0; mt < 2; mt++) {
                uint32_t off =
                    ((wM * 32 + mt * 16 + aRow) * PITCH + ks * 16 + aCol) * 2;
                ldm4(ah[mt], base + off);
                ldm4(al[mt], base + TILE_A + off);
            }
            #pragma unroll
            for (int ng = 0; ng < 4; ng++) {
                uint32_t bh[4], bl[4];
                uint32_t off =
                    ((wN * 64 + ng * 16 + bRow) * PITCH + ks * 16 + bCol) * 2;
                ldm4(bh, base + 2 * TILE_A + off);
                ldm4(bl, base + 2 * TILE_A + TILE_W + off);
                #pragma unroll
                for (int mt = 0; mt < 2; mt++)
                    #pragma unroll
                    for (int s = 0; s < 2; s++) {
                        int nt = ng * 2 + s;
                        mma16816(acc[mt][nt], ah[mt], &bh[s * 2]);  // hi*hi
                        mma16816(acc[mt][nt], al[mt], &bh[s * 2]);  // lo*hi
                        mma16816(acc[mt][nt], ah[mt], &bl[s * 2]);  // hi*lo
                    }
            }
        }
        __syncthreads();
        if (c + 2 < nchunks) load_chunk(c + 2, st);
    }

    // epilogue
    const int gid = lane >> 2, tig = lane & 3;
    float p[2][2] = {{0.f, 0.f}, {0.f, 0.f}};          // fused-gemv partials
    #pragma unroll
    for (int mt = 0; mt < 2; mt++) {
        int rg0 = row0 + wM * 32 + mt * 16 + gid;
        #pragma unroll
        for (int nt = 0; nt < 8; nt++) {
            int col = ncol0 + wN * 64 + nt * 8 + tig * 2;
            float b0 = __ldg(&bias[col]), b1 = __ldg(&bias[col + 1]);
            #pragma unroll
            for (int half = 0; half < 2; half++) {
                int row = rg0 + half * 8;
                float v0 = acc[mt][nt][half * 2]     + b0;
                float v1 = acc[mt][nt][half * 2 + 1] + b1;
                if (Rhi) {
                    uint32_t hw = *(const uint32_t*)(Rhi + (size_t)row * 512 + col);
                    uint32_t lw = *(const uint32_t*)(Rlo + (size_t)row * 512 + col);
                    __nv_bfloat162 hh = *reinterpret_cast<__nv_bfloat162*>(&hw);
                    __nv_bfloat162 ll = *reinterpret_cast<__nv_bfloat162*>(&lw);
                    v0 += __low2float(hh) + __low2float(ll);
                    v1 += __high2float(hh) + __high2float(ll);
                }
                v0 = fmaxf(v0, 0.f);
                v1 = fmaxf(v1, 0.f);
                if (Wv) {
                    p[mt][half] = fmaf(v0, __ldg(&Wv[col]),
                                  fmaf(v1, __ldg(&Wv[col + 1]), p[mt][half]));
                } else {
                    bf16 h0, l0, h1, l1;
                    split2(v0, h0, l0);
                    split2(v1, h1, l1);
                    *(uint32_t*)(Ohi + (size_t)row * 512 + col) = pack2(h0, h1);
                    *(uint32_t*)(Olo + (size_t)row * 512 + col) = pack2(l0, l1);
                }
            }
        }
    }
    if (Wv) {
        int slot = blockIdx.y * 2 + wN;                // 0..7, distinct col bands
        #pragma unroll
        for (int mt = 0; mt < 2; mt++)
            #pragma unroll
            for (int half = 0; half < 2; half++) {
                float v = p[mt][half];
                v += __shfl_xor_sync(0xffffffffu, v, 1);
                v += __shfl_xor_sync(0xffffffffu, v, 2);
                if (tig == 0) {
                    int row = row0 + wM * 32 + mt * 16 + half * 8 + gid;
                    acc8[(size_t)row * 8 + slot] = v;
                }
            }
    }
}

// ---------------------------------------------------------------- chain: sum partials + b2 (+prev), emit tail / final
__global__ void chain_kernel(const float* __restrict__ acc8, const float* __restrict__ b2,
                             const float* __restrict__ prev, float* __restrict__ acc,
                             bf16* __restrict__ thi, bf16* __restrict__ tlo,
                             float* __restrict__ fout) {
    int row = blockIdx.x * 256 + threadIdx.x;
    float s = __ldg(&b2[0]) + (prev ? prev[row] : 0.f);
    #pragma unroll
    for (int k = 0; k < 8; k++) s += acc8[(size_t)row * 8 + k];
    if (fout) { fout[row] = s; return; }
    acc[row] = s;
    bf16 h, l; split2(s, h, l);
    uint4 zero = make_uint4(0, 0, 0, 0);
    uint4 firstH = make_uint4(pack2(h, __float2bfloat16_rn(0.f)), 0, 0, 0);
    uint4 firstL = make_uint4(pack2(l, __float2bfloat16_rn(0.f)), 0, 0, 0);
    uint4* th = (uint4*)(thi + (size_t)row * 64);
    uint4* tl = (uint4*)(tlo + (size_t)row * 64);
    th[0] = firstH; tl[0] = firstL;
    #pragma unroll
    for (int u = 1; u < 8; u++) { th[u] = zero; tl[u] = zero; }
}

// ---------------------------------------------------------------- launch
extern "C" void kernel_launch(void* const* d_in, const int* in_sizes, int n_in,
                              void* d_out, int out_size) {
    const float* latent = (const float*)d_in[0];
    const float* pc     = (const float*)d_in[1];
    const float* W[3][3];
    const float* Bv[3][3];
    int p = 2;
    for (int s = 0; s < 3; s++)
        for (int j = 0; j < 3; j++) { W[s][j] = (const float*)d_in[p++]; Bv[s][j] = (const float*)d_in[p++]; }

    char* S = nullptr;
    cudaGetSymbolAddress((void**)&S, g_scratch);
    bf16* Lhi  = (bf16*)(S + OFF_L);
    bf16* Llo  = (bf16*)(S + OFF_L + PLANE);
    bf16* h0hi = (bf16*)(S + OFF_H0);
    bf16* h0lo = (bf16*)(S + OFF_H0 + PLANE);
    float* acc8 = (float*)(S + OFF_ACC8);
    bf16* thi[3], *tlo[3];
    for (int s = 0; s < 3; s++) {
        thi[s] = (bf16*)(S + OFF_T + (2 * s) * TAILP);
        tlo[s] = (bf16*)(S + OFF_T + (2 * s + 1) * TAILP);
    }
    bf16* w0hi[3], *w0lo[3], *w1hi[3], *w1lo[3];
    for (int s = 0; s < 3; s++) {
        w0hi[s] = (bf16*)(S + OFF_W0 + (2 * s) * W0P);
        w0lo[s] = (bf16*)(S + OFF_W0 + (2 * s + 1) * W0P);
        w1hi[s] = (bf16*)(S + OFF_W1 + (2 * s) * W1P);
        w1lo[s] = (bf16*)(S + OFF_W1 + (2 * s + 1) * W1P);
    }
    float* acc = (float*)(S + OFF_ACC);

    cudaFuncSetAttribute(gemm_kernel, cudaFuncAttributeMaxDynamicSharedMemorySize, GSMEM);

    int kdim0[3] = {FEATD + 12, FEATD + 1, FEATD + 1};
    dim3 ggrid(ROWSZ / 256, 512 / 128);

    // launch order chosen so ncu (-s 5 -c 1) captures the first big GEMM
    knn_kernel<<<BATCH * 8, 256>>>(pc, thi[0], tlo[0]);                                  // 0
    aconv_kernel<<<(ROWSZ * FEATD / 4) / 256, 256>>>(latent, Lhi, Llo);                  // 1
    wconv_kernel<<<(512 * KPAD0 + 255) / 256, 256>>>(W[0][0], w0hi[0], w0lo[0], kdim0[0], KPAD0); // 2
    wconv_kernel<<<(512 * KPAD1 + 255) / 256, 256>>>(W[0][1], w1hi[0], w1lo[0], 512, KPAD1);      // 3
    wconv_kernel<<<(512 * KPAD0 + 255) / 256, 256>>>(W[1][0], w0hi[1], w0lo[1], kdim0[1], KPAD0); // 4

    for (int s = 0; s < 3; s++) {
        if (s == 1) {
            wconv_kernel<<<(512 * KPAD1 + 255) / 256, 256>>>(W[1][1], w1hi[1], w1lo[1], 512, KPAD1);
            wconv_kernel<<<(512 * KPAD0 + 255) / 256, 256>>>(W[2][0], w0hi[2], w0lo[2], kdim0[2], KPAD0);
            wconv_kernel<<<(512 * KPAD1 + 255) / 256, 256>>>(W[2][1], w1hi[2], w1lo[2], 512, KPAD1);
        }
        // layer 0: h0 = relu([latent, tail] W0 + b0)
        gemm_kernel<<<ggrid, 512, GSMEM>>>(Lhi, Llo, thi[s], tlo[s],
                                           w0hi[s], w0lo[s], Bv[s][0],
                                           nullptr, nullptr, h0hi, h0lo,
                                           nullptr, nullptr, KPAD0, 9);
        // layer 1 fused with layer 2: partials of relu(h0 + h0 W1 + b1) . W2
        gemm_kernel<<<ggrid, 512, GSMEM>>>(h0hi, h0lo, nullptr, nullptr,
                                           w1hi[s], w1lo[s], Bv[s][1],
                                           h0hi, h0lo, nullptr, nullptr,
                                           W[s][2], acc8, KPAD1, 8);
        const float* prev = (s == 0) ? nullptr : acc;
        chain_kernel<<<ROWSZ / 256, 256>>>(acc8, Bv[s][2], prev, acc,
                                           (s < 2) ? thi[s + 1] : nullptr,
                                           (s < 2) ? tlo[s + 1] : nullptr,
                                           (s == 2) ? (float*)d_out : nullptr);
    }
}

// round 7
// speedup vs baseline: 1.3316x; 1.2880x over previous
#include <cuda_runtime.h>
#include <cuda_fp16.h>
#include <cstdint>

using f16 = __half;
#define DI __device__ __forceinline__

static constexpr int BATCH = 16;
static constexpr int NPTS  = 2048;
static constexpr int ROWSZ = BATCH * NPTS;        // 32768
static constexpr int FEATD = 512;
static constexpr int KPAD0 = 576;                 // 9 chunks of 64
static constexpr int KPAD1 = 512;                 // 8 chunks

static constexpr size_t PLANE = (size_t)ROWSZ * FEATD * 2;  // one f16 plane
static constexpr size_t TAILP = (size_t)ROWSZ * 64 * 2;
static constexpr size_t W0P   = (size_t)512 * KPAD0 * 2;
static constexpr size_t W1P   = (size_t)512 * KPAD1 * 2;

static constexpr size_t OFF_L    = 0;
static constexpr size_t OFF_H0   = 2 * PLANE;
static constexpr size_t OFF_ACC8 = 4 * PLANE;
static constexpr size_t OFF_T    = OFF_ACC8 + (size_t)ROWSZ * 8 * 4;
static constexpr size_t OFF_W0   = OFF_T + 6 * TAILP;
static constexpr size_t OFF_W1   = OFF_W0 + 3 * W0P;
static constexpr size_t OFF_ACC  = OFF_W1 + 3 * W1P;
static constexpr size_t SCRATCH  = OFF_ACC + (size_t)ROWSZ * 4;

__device__ __align__(128) char g_scratch[SCRATCH];

// ---------------------------------------------------------------- helpers
DI uint32_t s2u(const void* p) {
    uint32_t a;
    asm("{ .reg .u64 t; cvta.to.shared.u64 t, %1; cvt.u32.u64 %0, t; }"
        : "=r"(a) : "l"(p));
    return a;
}
DI void cpa16(uint32_t d, const void* s) {
    asm volatile("cp.async.cg.shared.global [%0], [%1], 16;" :: "r"(d), "l"(s));
}
DI void cpa_commit() { asm volatile("cp.async.commit_group;"); }
#define CPA_WAIT1() asm volatile("cp.async.wait_group 1;" ::: "memory")
#define CPA_WAIT0() asm volatile("cp.async.wait_group 0;" ::: "memory")

DI void ldm4(uint32_t* f, uint32_t a) {
    asm volatile("ldmatrix.sync.aligned.m8n8.x4.shared.b16 {%0,%1,%2,%3}, [%4];"
                 : "=r"(f[0]), "=r"(f[1]), "=r"(f[2]), "=r"(f[3]) : "r"(a));
}
DI void mma16816(float* d, const uint32_t* a, const uint32_t* b) {
    asm volatile(
        "mma.sync.aligned.m16n8k16.row.col.f32.f16.f16.f32 "
        "{%0,%1,%2,%3}, {%4,%5,%6,%7}, {%8,%9}, {%0,%1,%2,%3};"
        : "+f"(d[0]), "+f"(d[1]), "+f"(d[2]), "+f"(d[3])
        : "r"(a[0]), "r"(a[1]), "r"(a[2]), "r"(a[3]), "r"(b[0]), "r"(b[1]));
}

DI void split2(float x, f16& h, f16& l) {
    h = __float2half_rn(x);
    l = __float2half_rn(x - __half2float(h));
}
DI uint32_t pack2(f16 a, f16 b) {
    __half2 t = __halves2half2(a, b);
    return *reinterpret_cast<uint32_t*>(&t);
}
DI float dot3(float ax, float ay, float az, float bx, float by, float bz) {
    return fmaf(az, bz, fmaf(ay, by, ax * bx));
}

// ---------------------------------------------------------------- KNN + local cov
__global__ void knn_kernel(const float* __restrict__ pc, f16* __restrict__ thi,
                           f16* __restrict__ tlo) {
    __shared__ float sx[NPTS], sy[NPTS], sz[NPTS], sq[NPTS];
    int b = blockIdx.x >> 3, tile = blockIdx.x & 7;
    const float* p = pc + (size_t)b * NPTS * 3;
    for (int i = threadIdx.x; i < NPTS; i += 256) {
        float x = p[i * 3], y = p[i * 3 + 1], z = p[i * 3 + 2];
        sx[i] = x; sy[i] = y; sz[i] = z;
        sq[i] = dot3(x, y, z, x, y, z);
    }
    __syncthreads();
    int n = tile * 256 + threadIdx.x;
    float px = sx[n], py = sy[n], pz = sz[n], sn = sq[n];
    float v1 = -INFINITY, v2 = -INFINITY;
    int i1 = 0, i2 = 0;
    for (int m = 0; m < NPTS; m++) {
        float d = 2.f * dot3(px, py, pz, sx[m], sy[m], sz[m]) - sn - sq[m];
        if (d > v1) { v2 = v1; i2 = i1; v1 = d; i1 = m; }
        else if (d > v2) { v2 = d; i2 = m; }
    }
    float ax = sx[i1], ay = sy[i1], az = sz[i1];
    float bx = sx[i2], by = sy[i2], bz = sz[i2];
    float f[12] = { px, py, pz,
                    ax * bx, ax * by, ax * bz,
                    ay * bx, ay * by, ay * bz,
                    az * bx, az * by, az * bz };
    size_t row = (size_t)b * NPTS + n;
    for (int t = 0; t < 64; t++) {
        float v = (t < 12) ? f[t] : 0.f;
        f16 h, l; split2(v, h, l);
        thi[row * 64 + t] = h;
        tlo[row * 64 + t] = l;
    }
}

// ---------------------------------------------------------------- fp32 -> hi/lo planes
__global__ void aconv_kernel(const float* __restrict__ X, f16* __restrict__ hi,
                             f16* __restrict__ lo) {
    size_t i = ((size_t)blockIdx.x * blockDim.x + threadIdx.x) * 4;
    float4 v = *reinterpret_cast<const float4*>(X + i);
    f16 h0, l0, h1, l1, h2, l2, h3, l3;
    split2(v.x, h0, l0); split2(v.y, h1, l1);
    split2(v.z, h2, l2); split2(v.w, h3, l3);
    uint2 ho = make_uint2(pack2(h0, h1), pack2(h2, h3));
    uint2 lw = make_uint2(pack2(l0, l1), pack2(l2, l3));
    *reinterpret_cast<uint2*>(hi + i) = ho;
    *reinterpret_cast<uint2*>(lo + i) = lw;
}

// ---------------------------------------------------------------- all weights: transpose to [n][kpad] fp16
struct WJob { const float* W; f16* out; int kdim; int kpad; };

__global__ void wconv_all(WJob j0, WJob j1, WJob j2, WJob j3, WJob j4, WJob j5) {
    WJob jobs[6] = {j0, j1, j2, j3, j4, j5};
    int sizes[6], tot = 0;
    #pragma unroll
    for (int t = 0; t < 6; t++) { sizes[t] = 512 * jobs[t].kpad; tot += sizes[t]; }
    for (int idx = blockIdx.x * blockDim.x + threadIdx.x; idx < tot;
         idx += gridDim.x * blockDim.x) {
        int rem = idx, t = 0;
        while (rem >= sizes[t]) { rem -= sizes[t]; t++; }
        int kpad = jobs[t].kpad;
        int n = rem / kpad, k = rem - n * kpad;
        float v = (k < jobs[t].kdim) ? jobs[t].W[(size_t)k * 512 + n] : 0.f;
        jobs[t].out[rem] = __float2half_rn(v);
    }
}

// ---------------------------------------------------------------- big GEMM (mma.sync, fp16 2-term)
// CTA 256x128, 16 warps (8M x 2N), warp tile 32x64, K-chunk 64, 2-stage cp.async.
static constexpr int PITCH   = 72;                     // halves per smem row (+8 pad)
static constexpr int TILE_A  = 256 * PITCH * 2;        // 36864 B per A plane
static constexpr int TILE_W  = 128 * PITCH * 2;        // 18432 B for B plane
static constexpr int STAGE_B = 2 * TILE_A + TILE_W;    // 92160
static constexpr int GSMEM   = 2 * STAGE_B;            // 184320

__global__ __launch_bounds__(512, 1)
void gemm_kernel(const f16* __restrict__ Ahi, const f16* __restrict__ Alo,
                 const f16* __restrict__ Thi, const f16* __restrict__ Tlo,
                 const f16* __restrict__ Bw,
                 const float* __restrict__ bias,
                 const f16* __restrict__ Rhi, const f16* __restrict__ Rlo,
                 f16* __restrict__ Ohi, f16* __restrict__ Olo,
                 const float* __restrict__ Wv, float* __restrict__ acc8,
                 int kpad, int nchunks) {
    extern __shared__ char sm[];

    const int tid  = threadIdx.x;
    const int lane = tid & 31, wid = tid >> 5;
    const int wM = wid >> 1, wN = wid & 1;             // 8 x 2 warp grid
    const int row0  = blockIdx.x * 256;
    const int ncol0 = blockIdx.y * 128;

    const uint32_t smem0 = s2u(sm);

    auto load_chunk = [&](int c, int st) {
        uint32_t base = smem0 + st * STAGE_B;
        #pragma unroll
        for (int it = 0; it < 4; it++) {
            int i = tid + it * 512;                    // 0..2047
            int r = i >> 3, j = i & 7;                 // row 0..255, slot 0..7
            uint32_t dst = base + r * (PITCH * 2) + j * 16;
            const f16 *ph, *pl;
            if (c < 8) {
                ph = Ahi + (size_t)(row0 + r) * 512 + c * 64 + j * 8;
                pl = Alo + (size_t)(row0 + r) * 512 + c * 64 + j * 8;
            } else {
                ph = Thi + (size_t)(row0 + r) * 64 + j * 8;
                pl = Tlo + (size_t)(row0 + r) * 64 + j * 8;
            }
            cpa16(dst, ph);
            cpa16(dst + TILE_A, pl);
        }
        #pragma unroll
        for (int it = 0; it < 2; it++) {
            int i = tid + it * 512;                    // 0..1023
            int r = i >> 3, j = i & 7;                 // row 0..127
            uint32_t dst = base + 2 * TILE_A + r * (PITCH * 2) + j * 16;
            cpa16(dst, Bw + (size_t)(ncol0 + r) * kpad + c * 64 + j * 8);
        }
        cpa_commit();
    };

    float acc[2][8][4];
    #pragma unroll
    for (int a = 0; a < 2; a++)
        #pragma unroll
        for (int b = 0; b < 8; b++)
            #pragma unroll
            for (int k = 0; k < 4; k++) acc[a][b][k] = 0.f;

    const int quad = lane >> 3, r8 = lane & 7;
    const int aRow = r8 + ((quad & 1) << 3), aCol = (quad >> 1) << 3;
    const int bRow = r8 + ((quad >> 1) << 3), bCol = (quad & 1) << 3;

    load_chunk(0, 0);
    if (nchunks > 1) load_chunk(1, 1);

    for (int c = 0; c < nchunks; c++) {
        int st = c & 1;
        if (c + 1 < nchunks) { CPA_WAIT1(); } else { CPA_WAIT0(); }
        __syncthreads();

        uint32_t base = smem0 + st * STAGE_B;
        #pragma unroll
        for (int ks = 0; ks < 4; ks++) {
            uint32_t ah[2][4], al[2][4];
            #pragma unroll
            for (int mt = 0; mt < 2; mt++) {
                uint32_t off =
                    ((wM * 32 + mt * 16 + aRow) * PITCH + ks * 16 + aCol) * 2;
                ldm4(ah[mt], base + off);
                ldm4(al[mt], base + TILE_A + off);
            }
            #pragma unroll
            for (int ng = 0; ng < 4; ng++) {
                uint32_t bh[4];
                uint32_t off =
                    ((wN * 64 + ng * 16 + bRow) * PITCH + ks * 16 + bCol) * 2;
                ldm4(bh, base + 2 * TILE_A + off);
                #pragma unroll
                for (int mt = 0; mt < 2; mt++)
                    #pragma unroll
                    for (int s = 0; s < 2; s++) {
                        int nt = ng * 2 + s;
                        mma16816(acc[mt][nt], ah[mt], &bh[s * 2]);  // hi*W
                        mma16816(acc[mt][nt], al[mt], &bh[s * 2]);  // lo*W
                    }
            }
        }
        __syncthreads();
        if (c + 2 < nchunks) load_chunk(c + 2, st);
    }

    // epilogue
    const int gid = lane >> 2, tig = lane & 3;
    float p[2][2] = {{0.f, 0.f}, {0.f, 0.f}};          // fused-gemv partials
    #pragma unroll
    for (int mt = 0; mt < 2; mt++) {
        int rg0 = row0 + wM * 32 + mt * 16 + gid;
        #pragma unroll
        for (int nt = 0; nt < 8; nt++) {
            int col = ncol0 + wN * 64 + nt * 8 + tig * 2;
            float b0 = __ldg(&bias[col]), b1 = __ldg(&bias[col + 1]);
            #pragma unroll
            for (int half = 0; half < 2; half++) {
                int row = rg0 + half * 8;
                float v0 = acc[mt][nt][half * 2]     + b0;
                float v1 = acc[mt][nt][half * 2 + 1] + b1;
                if (Rhi) {
                    uint32_t hw = *(const uint32_t*)(Rhi + (size_t)row * 512 + col);
                    uint32_t lw = *(const uint32_t*)(Rlo + (size_t)row * 512 + col);
                    __half2 hh = *reinterpret_cast<__half2*>(&hw);
                    __half2 ll = *reinterpret_cast<__half2*>(&lw);
                    v0 += __low2float(hh) + __low2float(ll);
                    v1 += __high2float(hh) + __high2float(ll);
                }
                v0 = fmaxf(v0, 0.f);
                v1 = fmaxf(v1, 0.f);
                if (Wv) {
                    p[mt][half] = fmaf(v0, __ldg(&Wv[col]),
                                  fmaf(v1, __ldg(&Wv[col + 1]), p[mt][half]));
                } else {
                    f16 h0, l0, h1, l1;
                    split2(v0, h0, l0);
                    split2(v1, h1, l1);
                    *(uint32_t*)(Ohi + (size_t)row * 512 + col) = pack2(h0, h1);
                    *(uint32_t*)(Olo + (size_t)row * 512 + col) = pack2(l0, l1);
                }
            }
        }
    }
    if (Wv) {
        int slot = blockIdx.y * 2 + wN;                // 0..7, distinct col bands
        #pragma unroll
        for (int mt = 0; mt < 2; mt++)
            #pragma unroll
            for (int half = 0; half < 2; half++) {
                float v = p[mt][half];
                v += __shfl_xor_sync(0xffffffffu, v, 1);
                v += __shfl_xor_sync(0xffffffffu, v, 2);
                if (tig == 0) {
                    int row = row0 + wM * 32 + mt * 16 + half * 8 + gid;
                    acc8[(size_t)row * 8 + slot] = v;
                }
            }
    }
}

// ---------------------------------------------------------------- chain: sum partials + b2 (+prev), emit tail / final
__global__ void chain_kernel(const float* __restrict__ acc8, const float* __restrict__ b2,
                             const float* __restrict__ prev, float* __restrict__ acc,
                             f16* __restrict__ thi, f16* __restrict__ tlo,
                             float* __restrict__ fout) {
    int row = blockIdx.x * 256 + threadIdx.x;
    float s = __ldg(&b2[0]) + (prev ? prev[row] : 0.f);
    #pragma unroll
    for (int k = 0; k < 8; k++) s += acc8[(size_t)row * 8 + k];
    if (fout) { fout[row] = s; return; }
    acc[row] = s;
    f16 h, l; split2(s, h, l);
    uint4 zero = make_uint4(0, 0, 0, 0);
    uint4 firstH = make_uint4(pack2(h, __float2half_rn(0.f)), 0, 0, 0);
    uint4 firstL = make_uint4(pack2(l, __float2half_rn(0.f)), 0, 0, 0);
    uint4* th = (uint4*)(thi + (size_t)row * 64);
    uint4* tl = (uint4*)(tlo + (size_t)row * 64);
    th[0] = firstH; tl[0] = firstL;
    #pragma unroll
    for (int u = 1; u < 8; u++) { th[u] = zero; tl[u] = zero; }
}

// ---------------------------------------------------------------- launch
extern "C" void kernel_launch(void* const* d_in, const int* in_sizes, int n_in,
                              void* d_out, int out_size) {
    const float* latent = (const float*)d_in[0];
    const float* pc     = (const float*)d_in[1];
    const float* W[3][3];
    const float* Bv[3][3];
    int p = 2;
    for (int s = 0; s < 3; s++)
        for (int j = 0; j < 3; j++) { W[s][j] = (const float*)d_in[p++]; Bv[s][j] = (const float*)d_in[p++]; }

    char* S = nullptr;
    cudaGetSymbolAddress((void**)&S, g_scratch);
    f16* Lhi  = (f16*)(S + OFF_L);
    f16* Llo  = (f16*)(S + OFF_L + PLANE);
    f16* h0hi = (f16*)(S + OFF_H0);
    f16* h0lo = (f16*)(S + OFF_H0 + PLANE);
    float* acc8 = (float*)(S + OFF_ACC8);
    f16* thi[3], *tlo[3];
    for (int s = 0; s < 3; s++) {
        thi[s] = (f16*)(S + OFF_T + (2 * s) * TAILP);
        tlo[s] = (f16*)(S + OFF_T + (2 * s + 1) * TAILP);
    }
    f16* w0[3], *w1[3];
    for (int s = 0; s < 3; s++) {
        w0[s] = (f16*)(S + OFF_W0 + s * W0P);
        w1[s] = (f16*)(S + OFF_W1 + s * W1P);
    }
    float* acc = (float*)(S + OFF_ACC);

    cudaFuncSetAttribute(gemm_kernel, cudaFuncAttributeMaxDynamicSharedMemorySize, GSMEM);

    int kdim0[3] = {FEATD + 12, FEATD + 1, FEATD + 1};
    dim3 ggrid(ROWSZ / 256, 512 / 128);

    // launch order: indices 3 and 4 are GEMMs so ncu (-s 5, +2 harness offset) captures one
    knn_kernel<<<BATCH * 8, 256>>>(pc, thi[0], tlo[0]);                              // 0
    aconv_kernel<<<(ROWSZ * FEATD / 4) / 256, 256>>>(latent, Lhi, Llo);              // 1
    {
        WJob j0 = {W[0][0], w0[0], kdim0[0], KPAD0};
        WJob j1 = {W[0][1], w1[0], 512, KPAD1};
        WJob j2 = {W[1][0], w0[1], kdim0[1], KPAD0};
        WJob j3 = {W[1][1], w1[1], 512, KPAD1};
        WJob j4 = {W[2][0], w0[2], kdim0[2], KPAD0};
        WJob j5 = {W[2][1], w1[2], 512, KPAD1};
        wconv_all<<<1536, 256>>>(j0, j1, j2, j3, j4, j5);                            // 2
    }

    for (int s = 0; s < 3; s++) {
        // layer 0: h0 = relu([latent, tail] W0 + b0)
        gemm_kernel<<<ggrid, 512, GSMEM>>>(Lhi, Llo, thi[s], tlo[s],
                                           w0[s], Bv[s][0],
                                           nullptr, nullptr, h0hi, h0lo,
                                           nullptr, nullptr, KPAD0, 9);
        // layer 1 fused with layer 2: partials of relu(h0 + h0 W1 + b1) . W2
        gemm_kernel<<<ggrid, 512, GSMEM>>>(h0hi, h0lo, nullptr, nullptr,
                                           w1[s], Bv[s][1],
                                           h0hi, h0lo, nullptr, nullptr,
                                           W[s][2], acc8, KPAD1, 8);
        const float* prev = (s == 0) ? nullptr : acc;
        chain_kernel<<<ROWSZ / 256, 256>>>(acc8, Bv[s][2], prev, acc,
                                           (s < 2) ? thi[s + 1] : nullptr,
                                           (s < 2) ? tlo[s + 1] : nullptr,
                                           (s == 2) ? (float*)d_out : nullptr);
    }
}

// round 9
// speedup vs baseline: 1.3318x; 1.0002x over previous
#include <cuda_runtime.h>
#include <cuda_fp16.h>
#include <cstdint>

using f16 = __half;
#define DI __device__ __forceinline__

static constexpr int BATCH = 16;
static constexpr int NPTS  = 2048;
static constexpr int ROWSZ = BATCH * NPTS;        // 32768
static constexpr int FEATD = 512;
static constexpr int KPAD0 = 576;                 // 9 chunks of 64
static constexpr int KPAD1 = 512;                 // 8 chunks

static constexpr size_t PLANE = (size_t)ROWSZ * FEATD * 2;  // one f16 plane
static constexpr size_t TAILP = (size_t)ROWSZ * 64 * 2;
static constexpr size_t W0P   = (size_t)512 * KPAD0 * 2;
static constexpr size_t W1P   = (size_t)512 * KPAD1 * 2;

static constexpr size_t OFF_L    = 0;
static constexpr size_t OFF_H0   = 2 * PLANE;
static constexpr size_t OFF_ACC8 = 4 * PLANE;
static constexpr size_t OFF_T    = OFF_ACC8 + (size_t)ROWSZ * 8 * 4;
static constexpr size_t OFF_W0   = OFF_T + 6 * TAILP;
static constexpr size_t OFF_W1   = OFF_W0 + 3 * W0P;
static constexpr size_t OFF_ACC  = OFF_W1 + 3 * W1P;
static constexpr size_t SCRATCH  = OFF_ACC + (size_t)ROWSZ * 4;

__device__ __align__(128) char g_scratch[SCRATCH];

// ---------------------------------------------------------------- helpers
DI uint32_t s2u(const void* p) {
    uint32_t a;
    asm("{ .reg .u64 t; cvta.to.shared.u64 t, %1; cvt.u32.u64 %0, t; }"
        : "=r"(a) : "l"(p));
    return a;
}
DI void cpa16(uint32_t d, const void* s) {
    asm volatile("cp.async.cg.shared.global [%0], [%1], 16;" :: "r"(d), "l"(s));
}
DI void cpa_commit() { asm volatile("cp.async.commit_group;"); }
#define CPA_WAIT1() asm volatile("cp.async.wait_group 1;" ::: "memory")
#define CPA_WAIT0() asm volatile("cp.async.wait_group 0;" ::: "memory")

DI void ldm4(uint32_t* f, uint32_t a) {
    asm volatile("ldmatrix.sync.aligned.m8n8.x4.shared.b16 {%0,%1,%2,%3}, [%4];"
                 : "=r"(f[0]), "=r"(f[1]), "=r"(f[2]), "=r"(f[3]) : "r"(a));
}
DI void mma16816(float* d, const uint32_t* a, const uint32_t* b) {
    asm volatile(
        "mma.sync.aligned.m16n8k16.row.col.f32.f16.f16.f32 "
        "{%0,%1,%2,%3}, {%4,%5,%6,%7}, {%8,%9}, {%0,%1,%2,%3};"
        : "+f"(d[0]), "+f"(d[1]), "+f"(d[2]), "+f"(d[3])
        : "r"(a[0]), "r"(a[1]), "r"(a[2]), "r"(a[3]), "r"(b[0]), "r"(b[1]));
}

DI void split2(float x, f16& h, f16& l) {
    h = __float2half_rn(x);
    l = __float2half_rn(x - __half2float(h));
}
DI uint32_t pack2(f16 a, f16 b) {
    __half2 t = __halves2half2(a, b);
    return *reinterpret_cast<uint32_t*>(&t);
}
DI float dot3(float ax, float ay, float az, float bx, float by, float bz) {
    return fmaf(az, bz, fmaf(ay, by, ax * bx));
}

// ---------------------------------------------------------------- KNN + local cov
__global__ void knn_kernel(const float* __restrict__ pc, f16* __restrict__ thi,
                           f16* __restrict__ tlo) {
    __shared__ float sx[NPTS], sy[NPTS], sz[NPTS], sq[NPTS];
    int b = blockIdx.x >> 3, tile = blockIdx.x & 7;
    const float* p = pc + (size_t)b * NPTS * 3;
    for (int i = threadIdx.x; i < NPTS; i += 256) {
        float x = p[i * 3], y = p[i * 3 + 1], z = p[i * 3 + 2];
        sx[i] = x; sy[i] = y; sz[i] = z;
        sq[i] = dot3(x, y, z, x, y, z);
    }
    __syncthreads();
    int n = tile * 256 + threadIdx.x;
    float px = sx[n], py = sy[n], pz = sz[n], sn = sq[n];
    float v1 = -INFINITY, v2 = -INFINITY;
    int i1 = 0, i2 = 0;
    for (int m = 0; m < NPTS; m++) {
        float d = 2.f * dot3(px, py, pz, sx[m], sy[m], sz[m]) - sn - sq[m];
        if (d > v1) { v2 = v1; i2 = i1; v1 = d; i1 = m; }
        else if (d > v2) { v2 = d; i2 = m; }
    }
    float ax = sx[i1], ay = sy[i1], az = sz[i1];
    float bx = sx[i2], by = sy[i2], bz = sz[i2];
    float f[12] = { px, py, pz,
                    ax * bx, ax * by, ax * bz,
                    ay * bx, ay * by, ay * bz,
                    az * bx, az * by, az * bz };
    size_t row = (size_t)b * NPTS + n;
    for (int t = 0; t < 64; t++) {
        float v = (t < 12) ? f[t] : 0.f;
        f16 h, l; split2(v, h, l);
        thi[row * 64 + t] = h;
        tlo[row * 64 + t] = l;
    }
}

// ---------------------------------------------------------------- fp32 -> hi/lo planes
__global__ void aconv_kernel(const float* __restrict__ X, f16* __restrict__ hi,
                             f16* __restrict__ lo) {
    size_t i = ((size_t)blockIdx.x * blockDim.x + threadIdx.x) * 4;
    float4 v = *reinterpret_cast<const float4*>(X + i);
    f16 h0, l0, h1, l1, h2, l2, h3, l3;
    split2(v.x, h0, l0); split2(v.y, h1, l1);
    split2(v.z, h2, l2); split2(v.w, h3, l3);
    uint2 ho = make_uint2(pack2(h0, h1), pack2(h2, h3));
    uint2 lw = make_uint2(pack2(l0, l1), pack2(l2, l3));
    *reinterpret_cast<uint2*>(hi + i) = ho;
    *reinterpret_cast<uint2*>(lo + i) = lw;
}

// ---------------------------------------------------------------- all weights: transpose to [n][kpad] fp16
struct WJob { const float* W; f16* out; int kdim; int kpad; };

__global__ void wconv_all(WJob j0, WJob j1, WJob j2, WJob j3, WJob j4, WJob j5) {
    WJob jobs[6] = {j0, j1, j2, j3, j4, j5};
    int sizes[6], tot = 0;
    #pragma unroll
    for (int t = 0; t < 6; t++) { sizes[t] = 512 * jobs[t].kpad; tot += sizes[t]; }
    for (int idx = blockIdx.x * blockDim.x + threadIdx.x; idx < tot;
         idx += gridDim.x * blockDim.x) {
        int rem = idx, t = 0;
        while (rem >= sizes[t]) { rem -= sizes[t]; t++; }
        int kpad = jobs[t].kpad;
        int n = rem / kpad, k = rem - n * kpad;
        float v = (k < jobs[t].kdim) ? jobs[t].W[(size_t)k * 512 + n] : 0.f;
        jobs[t].out[rem] = __float2half_rn(v);
    }
}

// ---------------------------------------------------------------- big GEMM (mma.sync, fp16 2-term)
// CTA 256x128, 16 warps (8M x 2N), warp tile 32x64, K-chunk 64, 2-stage cp.async.
static constexpr int PITCH   = 72;                     // halves per smem row (+8 pad)
static constexpr int TILE_A  = 256 * PITCH * 2;        // 36864 B per A plane
static constexpr int TILE_W  = 128 * PITCH * 2;        // 18432 B for B plane
static constexpr int STAGE_B = 2 * TILE_A + TILE_W;    // 92160
static constexpr int GSMEM   = 2 * STAGE_B;            // 184320

__global__ __launch_bounds__(512, 1)
void gemm_kernel(const f16* __restrict__ Ahi, const f16* __restrict__ Alo,
                 const f16* __restrict__ Thi, const f16* __restrict__ Tlo,
                 const f16* __restrict__ Bw,
                 const float* __restrict__ bias,
                 const f16* __restrict__ Rhi, const f16* __restrict__ Rlo,
                 f16* __restrict__ Ohi, f16* __restrict__ Olo,
                 const float* __restrict__ Wv, float* __restrict__ acc8,
                 int kpad, int nchunks) {
    extern __shared__ char sm[];

    const int tid  = threadIdx.x;
    const int lane = tid & 31, wid = tid >> 5;
    const int wM = wid >> 1, wN = wid & 1;             // 8 x 2 warp grid
    const int row0  = blockIdx.x * 256;
    const int ncol0 = blockIdx.y * 128;

    const uint32_t smem0 = s2u(sm);

    auto load_chunk = [&](int c, int st) {
        uint32_t base = smem0 + st * STAGE_B;
        #pragma unroll
        for (int it = 0; it < 4; it++) {
            int i = tid + it * 512;                    // 0..2047
            int r = i >> 3, j = i & 7;                 // row 0..255, slot 0..7
            uint32_t dst = base + r * (PITCH * 2) + j * 16;
            const f16 *ph, *pl;
            if (c < 8) {
                ph = Ahi + (size_t)(row0 + r) * 512 + c * 64 + j * 8;
                pl = Alo + (size_t)(row0 + r) * 512 + c * 64 + j * 8;
            } else {
                ph = Thi + (size_t)(row0 + r) * 64 + j * 8;
                pl = Tlo + (size_t)(row0 + r) * 64 + j * 8;
            }
            cpa16(dst, ph);
            cpa16(dst + TILE_A, pl);
        }
        #pragma unroll
        for (int it = 0; it < 2; it++) {
            int i = tid + it * 512;                    // 0..1023
            int r = i >> 3, j = i & 7;                 // row 0..127
            uint32_t dst = base + 2 * TILE_A + r * (PITCH * 2) + j * 16;
            cpa16(dst, Bw + (size_t)(ncol0 + r) * kpad + c * 64 + j * 8);
        }
        cpa_commit();
    };

    float acc[2][8][4];
    #pragma unroll
    for (int a = 0; a < 2; a++)
        #pragma unroll
        for (int b = 0; b < 8; b++)
            #pragma unroll
            for (int k = 0; k < 4; k++) acc[a][b][k] = 0.f;

    const int quad = lane >> 3, r8 = lane & 7;
    const int aRow = r8 + ((quad & 1) << 3), aCol = (quad >> 1) << 3;
    const int bRow = r8 + ((quad >> 1) << 3), bCol = (quad & 1) << 3;

    load_chunk(0, 0);
    if (nchunks > 1) load_chunk(1, 1);

    for (int c = 0; c < nchunks; c++) {
        int st = c & 1;
        if (c + 1 < nchunks) { CPA_WAIT1(); } else { CPA_WAIT0(); }
        __syncthreads();

        uint32_t base = smem0 + st * STAGE_B;
        #pragma unroll
        for (int ks = 0; ks < 4; ks++) {
            uint32_t ah[2][4], al[2][4];
            #pragma unroll
            for (int mt = 0; mt < 2; mt++) {
                uint32_t off =
                    ((wM * 32 + mt * 16 + aRow) * PITCH + ks * 16 + aCol) * 2;
                ldm4(ah[mt], base + off);
                ldm4(al[mt], base + TILE_A + off);
            }
            #pragma unroll
            for (int ng = 0; ng < 4; ng++) {
                uint32_t bh[4];
                uint32_t off =
                    ((wN * 64 + ng * 16 + bRow) * PITCH + ks * 16 + bCol) * 2;
                ldm4(bh, base + 2 * TILE_A + off);
                #pragma unroll
                for (int mt = 0; mt < 2; mt++)
                    #pragma unroll
                    for (int s = 0; s < 2; s++) {
                        int nt = ng * 2 + s;
                        mma16816(acc[mt][nt], ah[mt], &bh[s * 2]);  // hi*W
                        mma16816(acc[mt][nt], al[mt], &bh[s * 2]);  // lo*W
                    }
            }
        }
        __syncthreads();
        if (c + 2 < nchunks) load_chunk(c + 2, st);
    }

    // epilogue
    const int gid = lane >> 2, tig = lane & 3;
    float p[2][2] = {{0.f, 0.f}, {0.f, 0.f}};          // fused-gemv partials
    #pragma unroll
    for (int mt = 0; mt < 2; mt++) {
        int rg0 = row0 + wM * 32 + mt * 16 + gid;
        #pragma unroll
        for (int nt = 0; nt < 8; nt++) {
            int col = ncol0 + wN * 64 + nt * 8 + tig * 2;
            float b0 = __ldg(&bias[col]), b1 = __ldg(&bias[col + 1]);
            #pragma unroll
            for (int half = 0; half < 2; half++) {
                int row = rg0 + half * 8;
                float v0 = acc[mt][nt][half * 2]     + b0;
                float v1 = acc[mt][nt][half * 2 + 1] + b1;
                if (Rhi) {
                    uint32_t hw = *(const uint32_t*)(Rhi + (size_t)row * 512 + col);
                    uint32_t lw = *(const uint32_t*)(Rlo + (size_t)row * 512 + col);
                    __half2 hh = *reinterpret_cast<__half2*>(&hw);
                    __half2 ll = *reinterpret_cast<__half2*>(&lw);
                    v0 += __low2float(hh) + __low2float(ll);
                    v1 += __high2float(hh) + __high2float(ll);
                }
                v0 = fmaxf(v0, 0.f);
                v1 = fmaxf(v1, 0.f);
                if (Wv) {
                    p[mt][half] = fmaf(v0, __ldg(&Wv[col]),
                                  fmaf(v1, __ldg(&Wv[col + 1]), p[mt][half]));
                } else {
                    f16 h0, l0, h1, l1;
                    split2(v0, h0, l0);
                    split2(v1, h1, l1);
                    *(uint32_t*)(Ohi + (size_t)row * 512 + col) = pack2(h0, h1);
                    *(uint32_t*)(Olo + (size_t)row * 512 + col) = pack2(l0, l1);
                }
            }
        }
    }
    if (Wv) {
        int slot = blockIdx.y * 2 + wN;                // 0..7, distinct col bands
        #pragma unroll
        for (int mt = 0; mt < 2; mt++)
            #pragma unroll
            for (int half = 0; half < 2; half++) {
                float v = p[mt][half];
                v += __shfl_xor_sync(0xffffffffu, v, 1);
                v += __shfl_xor_sync(0xffffffffu, v, 2);
                if (tig == 0) {
                    int row = row0 + wM * 32 + mt * 16 + half * 8 + gid;
                    acc8[(size_t)row * 8 + slot] = v;
                }
            }
    }
}

// ---------------------------------------------------------------- chain: sum partials + b2 (+prev), emit tail / final
__global__ void chain_kernel(const float* __restrict__ acc8, const float* __restrict__ b2,
                             const float* __restrict__ prev, float* __restrict__ acc,
                             f16* __restrict__ thi, f16* __restrict__ tlo,
                             float* __restrict__ fout) {
    int row = blockIdx.x * 256 + threadIdx.x;
    float s = __ldg(&b2[0]) + (prev ? prev[row] : 0.f);
    #pragma unroll
    for (int k = 0; k < 8; k++) s += acc8[(size_t)row * 8 + k];
    if (fout) { fout[row] = s; return; }
    acc[row] = s;
    f16 h, l; split2(s, h, l);
    uint4 zero = make_uint4(0, 0, 0, 0);
    uint4 firstH = make_uint4(pack2(h, __float2half_rn(0.f)), 0, 0, 0);
    uint4 firstL = make_uint4(pack2(l, __float2half_rn(0.f)), 0, 0, 0);
    uint4* th = (uint4*)(thi + (size_t)row * 64);
    uint4* tl = (uint4*)(tlo + (size_t)row * 64);
    th[0] = firstH; tl[0] = firstL;
    #pragma unroll
    for (int u = 1; u < 8; u++) { th[u] = zero; tl[u] = zero; }
}

// ---------------------------------------------------------------- launch
extern "C" void kernel_launch(void* const* d_in, const int* in_sizes, int n_in,
                              void* d_out, int out_size) {
    const float* latent = (const float*)d_in[0];
    const float* pc     = (const float*)d_in[1];
    const float* W[3][3];
    const float* Bv[3][3];
    int p = 2;
    for (int s = 0; s < 3; s++)
        for (int j = 0; j < 3; j++) { W[s][j] = (const float*)d_in[p++]; Bv[s][j] = (const float*)d_in[p++]; }

    char* S = nullptr;
    cudaGetSymbolAddress((void**)&S, g_scratch);
    f16* Lhi  = (f16*)(S + OFF_L);
    f16* Llo  = (f16*)(S + OFF_L + PLANE);
    f16* h0hi = (f16*)(S + OFF_H0);
    f16* h0lo = (f16*)(S + OFF_H0 + PLANE);
    float* acc8 = (float*)(S + OFF_ACC8);
    f16* thi[3], *tlo[3];
    for (int s = 0; s < 3; s++) {
        thi[s] = (f16*)(S + OFF_T + (2 * s) * TAILP);
        tlo[s] = (f16*)(S + OFF_T + (2 * s + 1) * TAILP);
    }
    f16* w0[3], *w1[3];
    for (int s = 0; s < 3; s++) {
        w0[s] = (f16*)(S + OFF_W0 + s * W0P);
        w1[s] = (f16*)(S + OFF_W1 + s * W1P);
    }
    float* acc = (float*)(S + OFF_ACC);

    cudaFuncSetAttribute(gemm_kernel, cudaFuncAttributeMaxDynamicSharedMemorySize, GSMEM);

    int kdim0[3] = {FEATD + 12, FEATD + 1, FEATD + 1};
    dim3 ggrid(ROWSZ / 256, 512 / 128);

    // launch order: indices 3 and 4 are GEMMs so ncu (-s 5, +2 harness offset) captures one
    knn_kernel<<<BATCH * 8, 256>>>(pc, thi[0], tlo[0]);                              // 0
    aconv_kernel<<<(ROWSZ * FEATD / 4) / 256, 256>>>(latent, Lhi, Llo);              // 1
    {
        WJob j0 = {W[0][0], w0[0], kdim0[0], KPAD0};
        WJob j1 = {W[0][1], w1[0], 512, KPAD1};
        WJob j2 = {W[1][0], w0[1], kdim0[1], KPAD0};
        WJob j3 = {W[1][1], w1[1], 512, KPAD1};
        WJob j4 = {W[2][0], w0[2], kdim0[2], KPAD0};
        WJob j5 = {W[2][1], w1[2], 512, KPAD1};
        wconv_all<<<1536, 256>>>(j0, j1, j2, j3, j4, j5);                            // 2
    }

    for (int s = 0; s < 3; s++) {
        // layer 0: h0 = relu([latent, tail] W0 + b0)
        gemm_kernel<<<ggrid, 512, GSMEM>>>(Lhi, Llo, thi[s], tlo[s],
                                           w0[s], Bv[s][0],
                                           nullptr, nullptr, h0hi, h0lo,
                                           nullptr, nullptr, KPAD0, 9);
        // layer 1 fused with layer 2: partials of relu(h0 + h0 W1 + b1) . W2
        gemm_kernel<<<ggrid, 512, GSMEM>>>(h0hi, h0lo, nullptr, nullptr,
                                           w1[s], Bv[s][1],
                                           h0hi, h0lo, nullptr, nullptr,
                                           W[s][2], acc8, KPAD1, 8);
        const float* prev = (s == 0) ? nullptr : acc;
        chain_kernel<<<ROWSZ / 256, 256>>>(acc8, Bv[s][2], prev, acc,
                                           (s < 2) ? thi[s + 1] : nullptr,
                                           (s < 2) ? tlo[s + 1] : nullptr,
                                           (s == 2) ? (float*)d_out : nullptr);
    }
}

// round 10
// speedup vs baseline: 1.6367x; 1.2289x over previous
#include <cuda_runtime.h>
#include <cuda_fp16.h>
#include <cstdint>

using f16 = __half;
#define DI __device__ __forceinline__

static constexpr int BATCH = 16;
static constexpr int NPTS  = 2048;
static constexpr int ROWSZ = BATCH * NPTS;        // 32768
static constexpr int FEATD = 512;
static constexpr int KPAD0 = 576;                 // 9 chunks of 64
static constexpr int KPAD1 = 512;                 // 8 chunks

static constexpr size_t PLANE = (size_t)ROWSZ * FEATD * 2;  // one f16 plane
static constexpr size_t TAILP = (size_t)ROWSZ * 64 * 2;
static constexpr size_t W0P   = (size_t)512 * KPAD0 * 2;
static constexpr size_t W1P   = (size_t)512 * KPAD1 * 2;

static constexpr size_t OFF_L    = 0;
static constexpr size_t OFF_H0   = 2 * PLANE;
static constexpr size_t OFF_ACC8 = 4 * PLANE;
static constexpr size_t OFF_T    = OFF_ACC8 + (size_t)ROWSZ * 8 * 4;
static constexpr size_t OFF_W0   = OFF_T + 6 * TAILP;
static constexpr size_t OFF_W1   = OFF_W0 + 3 * W0P;
static constexpr size_t OFF_ACC  = OFF_W1 + 3 * W1P;
static constexpr size_t SCRATCH  = OFF_ACC + (size_t)ROWSZ * 4;

__device__ __align__(128) char g_scratch[SCRATCH];

// ---------------------------------------------------------------- helpers
DI uint32_t s2u(const void* p) {
    uint32_t a;
    asm("{ .reg .u64 t; cvta.to.shared.u64 t, %1; cvt.u32.u64 %0, t; }"
        : "=r"(a) : "l"(p));
    return a;
}
DI void cpa16(uint32_t d, const void* s) {
    asm volatile("cp.async.cg.shared.global [%0], [%1], 16;" :: "r"(d), "l"(s));
}
DI void cpa_commit() { asm volatile("cp.async.commit_group;"); }
#define CPA_WAIT1() asm volatile("cp.async.wait_group 1;" ::: "memory")
#define CPA_WAIT0() asm volatile("cp.async.wait_group 0;" ::: "memory")

DI void ldm4(uint32_t* f, uint32_t a) {
    asm volatile("ldmatrix.sync.aligned.m8n8.x4.shared.b16 {%0,%1,%2,%3}, [%4];"
                 : "=r"(f[0]), "=r"(f[1]), "=r"(f[2]), "=r"(f[3]) : "r"(a));
}
DI void mma16816(float* d, const uint32_t* a, const uint32_t* b) {
    asm volatile(
        "mma.sync.aligned.m16n8k16.row.col.f32.f16.f16.f32 "
        "{%0,%1,%2,%3}, {%4,%5,%6,%7}, {%8,%9}, {%0,%1,%2,%3};"
        : "+f"(d[0]), "+f"(d[1]), "+f"(d[2]), "+f"(d[3])
        : "r"(a[0]), "r"(a[1]), "r"(a[2]), "r"(a[3]), "r"(b[0]), "r"(b[1]));
}

DI void split2(float x, f16& h, f16& l) {
    h = __float2half_rn(x);
    l = __float2half_rn(x - __half2float(h));
}
DI uint32_t pack2(f16 a, f16 b) {
    __half2 t = __halves2half2(a, b);
    return *reinterpret_cast<uint32_t*>(&t);
}
DI float dot3(float ax, float ay, float az, float bx, float by, float bz) {
    return fmaf(az, bz, fmaf(ay, by, ax * bx));
}

// ---------------------------------------------------------------- KNN + local cov
__global__ void knn_kernel(const float* __restrict__ pc, f16* __restrict__ thi,
                           f16* __restrict__ tlo) {
    __shared__ float sx[NPTS], sy[NPTS], sz[NPTS], sq[NPTS];
    int b = blockIdx.x >> 3, tile = blockIdx.x & 7;
    const float* p = pc + (size_t)b * NPTS * 3;
    for (int i = threadIdx.x; i < NPTS; i += 256) {
        float x = p[i * 3], y = p[i * 3 + 1], z = p[i * 3 + 2];
        sx[i] = x; sy[i] = y; sz[i] = z;
        sq[i] = dot3(x, y, z, x, y, z);
    }
    __syncthreads();
    int n = tile * 256 + threadIdx.x;
    float px = sx[n], py = sy[n], pz = sz[n], sn = sq[n];
    float v1 = -INFINITY, v2 = -INFINITY;
    int i1 = 0, i2 = 0;
    for (int m = 0; m < NPTS; m++) {
        float d = 2.f * dot3(px, py, pz, sx[m], sy[m], sz[m]) - sn - sq[m];
        if (d > v1) { v2 = v1; i2 = i1; v1 = d; i1 = m; }
        else if (d > v2) { v2 = d; i2 = m; }
    }
    float ax = sx[i1], ay = sy[i1], az = sz[i1];
    float bx = sx[i2], by = sy[i2], bz = sz[i2];
    float f[12] = { px, py, pz,
                    ax * bx, ax * by, ax * bz,
                    ay * bx, ay * by, ay * bz,
                    az * bx, az * by, az * bz };
    size_t row = (size_t)b * NPTS + n;
    for (int t = 0; t < 64; t++) {
        float v = (t < 12) ? f[t] : 0.f;
        f16 h, l; split2(v, h, l);
        thi[row * 64 + t] = h;
        tlo[row * 64 + t] = l;
    }
}

// ---------------------------------------------------------------- fp32 -> hi/lo planes
__global__ void aconv_kernel(const float* __restrict__ X, f16* __restrict__ hi,
                             f16* __restrict__ lo) {
    size_t i = ((size_t)blockIdx.x * blockDim.x + threadIdx.x) * 4;
    float4 v = *reinterpret_cast<const float4*>(X + i);
    f16 h0, l0, h1, l1, h2, l2, h3, l3;
    split2(v.x, h0, l0); split2(v.y, h1, l1);
    split2(v.z, h2, l2); split2(v.w, h3, l3);
    uint2 ho = make_uint2(pack2(h0, h1), pack2(h2, h3));
    uint2 lw = make_uint2(pack2(l0, l1), pack2(l2, l3));
    *reinterpret_cast<uint2*>(hi + i) = ho;
    *reinterpret_cast<uint2*>(lo + i) = lw;
}

// ---------------------------------------------------------------- all weights: transpose to [n][kpad] fp16
struct WJob { const float* W; f16* out; int kdim; int kpad; };

__global__ void wconv_all(WJob j0, WJob j1, WJob j2, WJob j3, WJob j4, WJob j5) {
    WJob jobs[6] = {j0, j1, j2, j3, j4, j5};
    int sizes[6], tot = 0;
    #pragma unroll
    for (int t = 0; t < 6; t++) { sizes[t] = 512 * jobs[t].kpad; tot += sizes[t]; }
    for (int idx = blockIdx.x * blockDim.x + threadIdx.x; idx < tot;
         idx += gridDim.x * blockDim.x) {
        int rem = idx, t = 0;
        while (rem >= sizes[t]) { rem -= sizes[t]; t++; }
        int kpad = jobs[t].kpad;
        int n = rem / kpad, k = rem - n * kpad;
        float v = (k < jobs[t].kdim) ? jobs[t].W[(size_t)k * 512 + n] : 0.f;
        jobs[t].out[rem] = __float2half_rn(v);
    }
}

// ---------------------------------------------------------------- big GEMM (mma.sync, fp16 2-term)
// CTA 128x128, 8 warps (4M x 2N), warp tile 32x64, K-chunk 64, 2-stage cp.async,
// 2 CTAs/SM for latency hiding.
static constexpr int PITCH   = 72;                     // halves per smem row (+8 pad)
static constexpr int TILE_A  = 128 * PITCH * 2;        // 18432 B per A plane
static constexpr int TILE_W  = 128 * PITCH * 2;        // 18432 B for B plane
static constexpr int STAGE_B = 2 * TILE_A + TILE_W;    // 55296
static constexpr int GSMEM   = 2 * STAGE_B;            // 110592 (x2 CTAs = 216KB/SM)

__global__ __launch_bounds__(256, 2)
void gemm_kernel(const f16* __restrict__ Ahi, const f16* __restrict__ Alo,
                 const f16* __restrict__ Thi, const f16* __restrict__ Tlo,
                 const f16* __restrict__ Bw,
                 const float* __restrict__ bias,
                 const f16* __restrict__ Rhi, const f16* __restrict__ Rlo,
                 f16* __restrict__ Ohi, f16* __restrict__ Olo,
                 const float* __restrict__ Wv, float* __restrict__ acc8,
                 int kpad, int nchunks) {
    extern __shared__ char sm[];

    const int tid  = threadIdx.x;
    const int lane = tid & 31, wid = tid >> 5;
    const int wM = wid >> 1, wN = wid & 1;             // 4 x 2 warp grid
    const int row0  = blockIdx.x * 128;
    const int ncol0 = blockIdx.y * 128;

    const uint32_t smem0 = s2u(sm);

    auto load_chunk = [&](int c, int st) {
        uint32_t base = smem0 + st * STAGE_B;
        #pragma unroll
        for (int it = 0; it < 4; it++) {
            int i = tid + it * 256;                    // 0..1023
            int r = i >> 3, j = i & 7;                 // row 0..127, slot 0..7
            uint32_t dst = base + r * (PITCH * 2) + j * 16;
            const f16 *ph, *pl;
            if (c < 8) {
                ph = Ahi + (size_t)(row0 + r) * 512 + c * 64 + j * 8;
                pl = Alo + (size_t)(row0 + r) * 512 + c * 64 + j * 8;
            } else {
                ph = Thi + (size_t)(row0 + r) * 64 + j * 8;
                pl = Tlo + (size_t)(row0 + r) * 64 + j * 8;
            }
            cpa16(dst, ph);
            cpa16(dst + TILE_A, pl);
            uint32_t dstB = base + 2 * TILE_A + r * (PITCH * 2) + j * 16;
            cpa16(dstB, Bw + (size_t)(ncol0 + r) * kpad + c * 64 + j * 8);
        }
        cpa_commit();
    };

    float acc[2][8][4];
    #pragma unroll
    for (int a = 0; a < 2; a++)
        #pragma unroll
        for (int b = 0; b < 8; b++)
            #pragma unroll
            for (int k = 0; k < 4; k++) acc[a][b][k] = 0.f;

    const int quad = lane >> 3, r8 = lane & 7;
    const int aRow = r8 + ((quad & 1) << 3), aCol = (quad >> 1) << 3;
    const int bRow = r8 + ((quad >> 1) << 3), bCol = (quad & 1) << 3;

    load_chunk(0, 0);
    if (nchunks > 1) load_chunk(1, 1);

    for (int c = 0; c < nchunks; c++) {
        int st = c & 1;
        if (c + 1 < nchunks) { CPA_WAIT1(); } else { CPA_WAIT0(); }
        __syncthreads();

        uint32_t base = smem0 + st * STAGE_B;
        uint32_t baseB = base + 2 * TILE_A;
        #pragma unroll
        for (int ks = 0; ks < 4; ks++) {
            uint32_t ah[2][4], al[2][4];
            #pragma unroll
            for (int mt = 0; mt < 2; mt++) {
                uint32_t off =
                    ((wM * 32 + mt * 16 + aRow) * PITCH + ks * 16 + aCol) * 2;
                ldm4(ah[mt], base + off);
                ldm4(al[mt], base + TILE_A + off);
            }
            // double-buffered B ldmatrix, hi-term block then lo-term block
            uint32_t bb[2][4];
            {
                uint32_t off = ((wN * 64 + bRow) * PITCH + ks * 16 + bCol) * 2;
                ldm4(bb[0], baseB + off);
            }
            #pragma unroll
            for (int ng = 0; ng < 4; ng++) {
                int cur = ng & 1;
                if (ng < 3) {
                    uint32_t off =
                        ((wN * 64 + (ng + 1) * 16 + bRow) * PITCH + ks * 16 + bCol) * 2;
                    ldm4(bb[cur ^ 1], baseB + off);
                }
                #pragma unroll
                for (int mt = 0; mt < 2; mt++)
                    #pragma unroll
                    for (int s = 0; s < 2; s++)
                        mma16816(acc[mt][ng * 2 + s], ah[mt], &bb[cur][s * 2]);
                #pragma unroll
                for (int mt = 0; mt < 2; mt++)
                    #pragma unroll
                    for (int s = 0; s < 2; s++)
                        mma16816(acc[mt][ng * 2 + s], al[mt], &bb[cur][s * 2]);
            }
        }
        __syncthreads();
        if (c + 2 < nchunks) load_chunk(c + 2, st);
    }

    // epilogue
    const int gid = lane >> 2, tig = lane & 3;
    float p[2][2] = {{0.f, 0.f}, {0.f, 0.f}};          // fused-gemv partials
    #pragma unroll
    for (int mt = 0; mt < 2; mt++) {
        int rg0 = row0 + wM * 32 + mt * 16 + gid;
        #pragma unroll
        for (int nt = 0; nt < 8; nt++) {
            int col = ncol0 + wN * 64 + nt * 8 + tig * 2;
            float b0 = __ldg(&bias[col]), b1 = __ldg(&bias[col + 1]);
            #pragma unroll
            for (int half = 0; half < 2; half++) {
                int row = rg0 + half * 8;
                float v0 = acc[mt][nt][half * 2]     + b0;
                float v1 = acc[mt][nt][half * 2 + 1] + b1;
                if (Rhi) {
                    uint32_t hw = *(const uint32_t*)(Rhi + (size_t)row * 512 + col);
                    uint32_t lw = *(const uint32_t*)(Rlo + (size_t)row * 512 + col);
                    __half2 hh = *reinterpret_cast<__half2*>(&hw);
                    __half2 ll = *reinterpret_cast<__half2*>(&lw);
                    v0 += __low2float(hh) + __low2float(ll);
                    v1 += __high2float(hh) + __high2float(ll);
                }
                v0 = fmaxf(v0, 0.f);
                v1 = fmaxf(v1, 0.f);
                if (Wv) {
                    p[mt][half] = fmaf(v0, __ldg(&Wv[col]),
                                  fmaf(v1, __ldg(&Wv[col + 1]), p[mt][half]));
                } else {
                    f16 h0, l0, h1, l1;
                    split2(v0, h0, l0);
                    split2(v1, h1, l1);
                    *(uint32_t*)(Ohi + (size_t)row * 512 + col) = pack2(h0, h1);
                    *(uint32_t*)(Olo + (size_t)row * 512 + col) = pack2(l0, l1);
                }
            }
        }
    }
    if (Wv) {
        int slot = blockIdx.y * 2 + wN;                // 0..7, distinct col bands
        #pragma unroll
        for (int mt = 0; mt < 2; mt++)
            #pragma unroll
            for (int half = 0; half < 2; half++) {
                float v = p[mt][half];
                v += __shfl_xor_sync(0xffffffffu, v, 1);
                v += __shfl_xor_sync(0xffffffffu, v, 2);
                if (tig == 0) {
                    int row = row0 + wM * 32 + mt * 16 + half * 8 + gid;
                    acc8[(size_t)row * 8 + slot] = v;
                }
            }
    }
}

// ---------------------------------------------------------------- chain: sum partials + b2 (+prev), emit tail / final
__global__ void chain_kernel(const float* __restrict__ acc8, const float* __restrict__ b2,
                             const float* __restrict__ prev, float* __restrict__ acc,
                             f16* __restrict__ thi, f16* __restrict__ tlo,
                             float* __restrict__ fout) {
    int row = blockIdx.x * 256 + threadIdx.x;
    float s = __ldg(&b2[0]) + (prev ? prev[row] : 0.f);
    #pragma unroll
    for (int k = 0; k < 8; k++) s += acc8[(size_t)row * 8 + k];
    if (fout) { fout[row] = s; return; }
    acc[row] = s;
    f16 h, l; split2(s, h, l);
    uint4 zero = make_uint4(0, 0, 0, 0);
    uint4 firstH = make_uint4(pack2(h, __float2half_rn(0.f)), 0, 0, 0);
    uint4 firstL = make_uint4(pack2(l, __float2half_rn(0.f)), 0, 0, 0);
    uint4* th = (uint4*)(thi + (size_t)row * 64);
    uint4* tl = (uint4*)(tlo + (size_t)row * 64);
    th[0] = firstH; tl[0] = firstL;
    #pragma unroll
    for (int u = 1; u < 8; u++) { th[u] = zero; tl[u] = zero; }
}

// ---------------------------------------------------------------- launch
extern "C" void kernel_launch(void* const* d_in, const int* in_sizes, int n_in,
                              void* d_out, int out_size) {
    const float* latent = (const float*)d_in[0];
    const float* pc     = (const float*)d_in[1];
    const float* W[3][3];
    const float* Bv[3][3];
    int p = 2;
    for (int s = 0; s < 3; s++)
        for (int j = 0; j < 3; j++) { W[s][j] = (const float*)d_in[p++]; Bv[s][j] = (const float*)d_in[p++]; }

    char* S = nullptr;
    cudaGetSymbolAddress((void**)&S, g_scratch);
    f16* Lhi  = (f16*)(S + OFF_L);
    f16* Llo  = (f16*)(S + OFF_L + PLANE);
    f16* h0hi = (f16*)(S + OFF_H0);
    f16* h0lo = (f16*)(S + OFF_H0 + PLANE);
    float* acc8 = (float*)(S + OFF_ACC8);
    f16* thi[3], *tlo[3];
    for (int s = 0; s < 3; s++) {
        thi[s] = (f16*)(S + OFF_T + (2 * s) * TAILP);
        tlo[s] = (f16*)(S + OFF_T + (2 * s + 1) * TAILP);
    }
    f16* w0[3], *w1[3];
    for (int s = 0; s < 3; s++) {
        w0[s] = (f16*)(S + OFF_W0 + s * W0P);
        w1[s] = (f16*)(S + OFF_W1 + s * W1P);
    }
    float* acc = (float*)(S + OFF_ACC);

    cudaFuncSetAttribute(gemm_kernel, cudaFuncAttributeMaxDynamicSharedMemorySize, GSMEM);

    int kdim0[3] = {FEATD + 12, FEATD + 1, FEATD + 1};
    dim3 ggrid(ROWSZ / 128, 512 / 128);

    // launch order: indices 3 and 4 are GEMMs so ncu (-s 5, +2 harness offset) captures one
    knn_kernel<<<BATCH * 8, 256>>>(pc, thi[0], tlo[0]);                              // 0
    aconv_kernel<<<(ROWSZ * FEATD / 4) / 256, 256>>>(latent, Lhi, Llo);              // 1
    {
        WJob j0 = {W[0][0], w0[0], kdim0[0], KPAD0};
        WJob j1 = {W[0][1], w1[0], 512, KPAD1};
        WJob j2 = {W[1][0], w0[1], kdim0[1], KPAD0};
        WJob j3 = {W[1][1], w1[1], 512, KPAD1};
        WJob j4 = {W[2][0], w0[2], kdim0[2], KPAD0};
        WJob j5 = {W[2][1], w1[2], 512, KPAD1};
        wconv_all<<<1536, 256>>>(j0, j1, j2, j3, j4, j5);                            // 2
    }

    for (int s = 0; s < 3; s++) {
        // layer 0: h0 = relu([latent, tail] W0 + b0)
        gemm_kernel<<<ggrid, 256, GSMEM>>>(Lhi, Llo, thi[s], tlo[s],
                                           w0[s], Bv[s][0],
                                           nullptr, nullptr, h0hi, h0lo,
                                           nullptr, nullptr, KPAD0, 9);
        // layer 1 fused with layer 2: partials of relu(h0 + h0 W1 + b1) . W2
        gemm_kernel<<<ggrid, 256, GSMEM>>>(h0hi, h0lo, nullptr, nullptr,
                                           w1[s], Bv[s][1],
                                           h0hi, h0lo, nullptr, nullptr,
                                           W[s][2], acc8, KPAD1, 8);
        const float* prev = (s == 0) ? nullptr : acc;
        chain_kernel<<<ROWSZ / 256, 256>>>(acc8, Bv[s][2], prev, acc,
                                           (s < 2) ? thi[s + 1] : nullptr,
                                           (s < 2) ? tlo[s + 1] : nullptr,
                                           (s == 2) ? (float*)d_out : nullptr);
    }
}

// round 12
// speedup vs baseline: 2.6429x; 1.6148x over previous
#include <cuda_runtime.h>
#include <cuda_fp16.h>
#include <cstdint>

using f16 = __half;
#define DI __device__ __forceinline__

static constexpr int BATCH = 16;
static constexpr int NPTS  = 2048;
static constexpr int ROWSZ = BATCH * NPTS;        // 32768
static constexpr int FEATD = 512;
static constexpr int KPAD0 = 576;                 // 9 chunks of 64
static constexpr int KPAD1 = 512;                 // 8 chunks

static constexpr size_t PLANE = (size_t)ROWSZ * FEATD * 2;  // one f16 plane
static constexpr size_t TAILP = (size_t)ROWSZ * 64 * 2;
static constexpr size_t W0P   = (size_t)512 * KPAD0 * 2;
static constexpr size_t W1P   = (size_t)512 * KPAD1 * 2;

static constexpr size_t OFF_L    = 0;
static constexpr size_t OFF_H0   = PLANE;
static constexpr size_t OFF_ACC8 = 2 * PLANE;
static constexpr size_t OFF_T    = OFF_ACC8 + (size_t)ROWSZ * 8 * 4;
static constexpr size_t OFF_W0   = OFF_T + 3 * TAILP;
static constexpr size_t OFF_W1   = OFF_W0 + 3 * W0P;
static constexpr size_t OFF_ACC  = OFF_W1 + 3 * W1P;
static constexpr size_t SCRATCH  = OFF_ACC + (size_t)ROWSZ * 4;

__device__ __align__(128) char g_scratch[SCRATCH];

// ---------------------------------------------------------------- helpers
DI uint32_t s2u(const void* p) {
    uint32_t a;
    asm("{ .reg .u64 t; cvta.to.shared.u64 t, %1; cvt.u32.u64 %0, t; }"
        : "=r"(a) : "l"(p));
    return a;
}
DI void cpa16(uint32_t d, const void* s) {
    asm volatile("cp.async.cg.shared.global [%0], [%1], 16;" :: "r"(d), "l"(s));
}
DI void cpa_commit() { asm volatile("cp.async.commit_group;"); }
#define CPA_WAIT1() asm volatile("cp.async.wait_group 1;" ::: "memory")
#define CPA_WAIT0() asm volatile("cp.async.wait_group 0;" ::: "memory")

DI void ldm4(uint32_t* f, uint32_t a) {
    asm volatile("ldmatrix.sync.aligned.m8n8.x4.shared.b16 {%0,%1,%2,%3}, [%4];"
                 : "=r"(f[0]), "=r"(f[1]), "=r"(f[2]), "=r"(f[3]) : "r"(a));
}
DI void mma16816(float* d, const uint32_t* a, const uint32_t* b) {
    asm volatile(
        "mma.sync.aligned.m16n8k16.row.col.f32.f16.f16.f32 "
        "{%0,%1,%2,%3}, {%4,%5,%6,%7}, {%8,%9}, {%0,%1,%2,%3};"
        : "+f"(d[0]), "+f"(d[1]), "+f"(d[2]), "+f"(d[3])
        : "r"(a[0]), "r"(a[1]), "r"(a[2]), "r"(a[3]), "r"(b[0]), "r"(b[1]));
}

DI uint32_t pack2(f16 a, f16 b) {
    __half2 t = __halves2half2(a, b);
    return *reinterpret_cast<uint32_t*>(&t);
}
DI float dot3(float ax, float ay, float az, float bx, float by, float bz) {
    return fmaf(az, bz, fmaf(ay, by, ax * bx));
}

// ---------------------------------------------------------------- KNN + local cov
__global__ void knn_kernel(const float* __restrict__ pc, f16* __restrict__ thi) {
    __shared__ float sx[NPTS], sy[NPTS], sz[NPTS], sq[NPTS];
    int b = blockIdx.x >> 3, tile = blockIdx.x & 7;
    const float* p = pc + (size_t)b * NPTS * 3;
    for (int i = threadIdx.x; i < NPTS; i += 256) {
        float x = p[i * 3], y = p[i * 3 + 1], z = p[i * 3 + 2];
        sx[i] = x; sy[i] = y; sz[i] = z;
        sq[i] = dot3(x, y, z, x, y, z);
    }
    __syncthreads();
    int n = tile * 256 + threadIdx.x;
    float px = sx[n], py = sy[n], pz = sz[n], sn = sq[n];
    float v1 = -INFINITY, v2 = -INFINITY;
    int i1 = 0, i2 = 0;
    for (int m = 0; m < NPTS; m++) {
        float d = 2.f * dot3(px, py, pz, sx[m], sy[m], sz[m]) - sn - sq[m];
        if (d > v1) { v2 = v1; i2 = i1; v1 = d; i1 = m; }
        else if (d > v2) { v2 = d; i2 = m; }
    }
    float ax = sx[i1], ay = sy[i1], az = sz[i1];
    float bx = sx[i2], by = sy[i2], bz = sz[i2];
    float f[12] = { px, py, pz,
                    ax * bx, ax * by, ax * bz,
                    ay * bx, ay * by, ay * bz,
                    az * bx, az * by, az * bz };
    size_t row = (size_t)b * NPTS + n;
    for (int t = 0; t < 64; t++)
        thi[row * 64 + t] = __float2half_rn((t < 12) ? f[t] : 0.f);
}

// ---------------------------------------------------------------- fp32 -> fp16 plane
__global__ void aconv_kernel(const float* __restrict__ X, f16* __restrict__ hi) {
    size_t i = ((size_t)blockIdx.x * blockDim.x + threadIdx.x) * 4;
    float4 v = *reinterpret_cast<const float4*>(X + i);
    uint2 ho = make_uint2(pack2(__float2half_rn(v.x), __float2half_rn(v.y)),
                          pack2(__float2half_rn(v.z), __float2half_rn(v.w)));
    *reinterpret_cast<uint2*>(hi + i) = ho;
}

// ---------------------------------------------------------------- all weights: transpose to [n][kpad] fp16
struct WJob { const float* W; f16* out; int kdim; int kpad; };

__global__ void wconv_all(WJob j0, WJob j1, WJob j2, WJob j3, WJob j4, WJob j5) {
    WJob jobs[6] = {j0, j1, j2, j3, j4, j5};
    int sizes[6], tot = 0;
    #pragma unroll
    for (int t = 0; t < 6; t++) { sizes[t] = 512 * jobs[t].kpad; tot += sizes[t]; }
    for (int idx = blockIdx.x * blockDim.x + threadIdx.x; idx < tot;
         idx += gridDim.x * blockDim.x) {
        int rem = idx, t = 0;
        while (rem >= sizes[t]) { rem -= sizes[t]; t++; }
        int kpad = jobs[t].kpad;
        int n = rem / kpad, k = rem - n * kpad;
        float v = (k < jobs[t].kdim) ? jobs[t].W[(size_t)k * 512 + n] : 0.f;
        jobs[t].out[rem] = __float2half_rn(v);
    }
}

// ---------------------------------------------------------------- big GEMM (mma.sync, fp16 1-term)
// CTA 128x128, 8 warps (4M x 2N), warp tile 32x64, K-chunk 64, 2-stage cp.async,
// 2 CTAs/SM.
static constexpr int PITCH   = 72;                     // halves per smem row (+8 pad)
static constexpr int TILE_A  = 128 * PITCH * 2;        // 18432 B
static constexpr int TILE_W  = 128 * PITCH * 2;        // 18432 B
static constexpr int STAGE_B = TILE_A + TILE_W;        // 36864
static constexpr int GSMEM   = 2 * STAGE_B;            // 73728 (x2 CTAs = 144KB/SM)

__global__ __launch_bounds__(256, 2)
void gemm_kernel(const f16* __restrict__ Ahi,
                 const f16* __restrict__ Thi,
                 const f16* __restrict__ Bw,
                 const float* __restrict__ bias,
                 const f16* __restrict__ Rhi,
                 f16* __restrict__ Ohi,
                 const float* __restrict__ Wv, float* __restrict__ acc8,
                 int kpad, int nchunks) {
    extern __shared__ char sm[];

    const int tid  = threadIdx.x;
    const int lane = tid & 31, wid = tid >> 5;
    const int wM = wid >> 1, wN = wid & 1;             // 4 x 2 warp grid
    const int row0  = blockIdx.x * 128;
    const int ncol0 = blockIdx.y * 128;

    const uint32_t smem0 = s2u(sm);

    auto load_chunk = [&](int c, int st) {
        uint32_t base = smem0 + st * STAGE_B;
        #pragma unroll
        for (int it = 0; it < 4; it++) {
            int i = tid + it * 256;                    // 0..1023
            int r = i >> 3, j = i & 7;                 // row 0..127, slot 0..7
            uint32_t dst = base + r * (PITCH * 2) + j * 16;
            const f16* ph;
            if (c < 8)
                ph = Ahi + (size_t)(row0 + r) * 512 + c * 64 + j * 8;
            else
                ph = Thi + (size_t)(row0 + r) * 64 + j * 8;
            cpa16(dst, ph);
            uint32_t dstB = base + TILE_A + r * (PITCH * 2) + j * 16;
            cpa16(dstB, Bw + (size_t)(ncol0 + r) * kpad + c * 64 + j * 8);
        }
        cpa_commit();
    };

    float acc[2][8][4];
    #pragma unroll
    for (int a = 0; a < 2; a++)
        #pragma unroll
        for (int b = 0; b < 8; b++)
            #pragma unroll
            for (int k = 0; k < 4; k++) acc[a][b][k] = 0.f;

    const int quad = lane >> 3, r8 = lane & 7;
    const int aRow = r8 + ((quad & 1) << 3), aCol = (quad >> 1) << 3;
    const int bRow = r8 + ((quad >> 1) << 3), bCol = (quad & 1) << 3;

    load_chunk(0, 0);
    if (nchunks > 1) load_chunk(1, 1);

    for (int c = 0; c < nchunks; c++) {
        int st = c & 1;
        if (c + 1 < nchunks) { CPA_WAIT1(); } else { CPA_WAIT0(); }
        __syncthreads();

        uint32_t base = smem0 + st * STAGE_B;
        uint32_t baseB = base + TILE_A;
        #pragma unroll
        for (int ks = 0; ks < 4; ks++) {
            uint32_t ah[2][4];
            #pragma unroll
            for (int mt = 0; mt < 2; mt++) {
                uint32_t off =
                    ((wM * 32 + mt * 16 + aRow) * PITCH + ks * 16 + aCol) * 2;
                ldm4(ah[mt], base + off);
            }
            // double-buffered B ldmatrix
            uint32_t bb[2][4];
            {
                uint32_t off = ((wN * 64 + bRow) * PITCH + ks * 16 + bCol) * 2;
                ldm4(bb[0], baseB + off);
            }
            #pragma unroll
            for (int ng = 0; ng < 4; ng++) {
                int cur = ng & 1;
                if (ng < 3) {
                    uint32_t off =
                        ((wN * 64 + (ng + 1) * 16 + bRow) * PITCH + ks * 16 + bCol) * 2;
                    ldm4(bb[cur ^ 1], baseB + off);
                }
                #pragma unroll
                for (int mt = 0; mt < 2; mt++)
                    #pragma unroll
                    for (int s = 0; s < 2; s++)
                        mma16816(acc[mt][ng * 2 + s], ah[mt], &bb[cur][s * 2]);
            }
        }
        __syncthreads();
        if (c + 2 < nchunks) load_chunk(c + 2, st);
    }

    // epilogue
    const int gid = lane >> 2, tig = lane & 3;
    float p[2][2] = {{0.f, 0.f}, {0.f, 0.f}};          // fused-gemv partials
    #pragma unroll
    for (int mt = 0; mt < 2; mt++) {
        int rg0 = row0 + wM * 32 + mt * 16 + gid;
        #pragma unroll
        for (int nt = 0; nt < 8; nt++) {
            int col = ncol0 + wN * 64 + nt * 8 + tig * 2;
            float b0 = __ldg(&bias[col]), b1 = __ldg(&bias[col + 1]);
            #pragma unroll
            for (int half = 0; half < 2; half++) {
                int row = rg0 + half * 8;
                float v0 = acc[mt][nt][half * 2]     + b0;
                float v1 = acc[mt][nt][half * 2 + 1] + b1;
                if (Rhi) {
                    uint32_t hw = *(const uint32_t*)(Rhi + (size_t)row * 512 + col);
                    __half2 hh = *reinterpret_cast<__half2*>(&hw);
                    v0 += __low2float(hh);
                    v1 += __high2float(hh);
                }
                v0 = fmaxf(v0, 0.f);
                v1 = fmaxf(v1, 0.f);
                if (Wv) {
                    p[mt][half] = fmaf(v0, __ldg(&Wv[col]),
                                  fmaf(v1, __ldg(&Wv[col + 1]), p[mt][half]));
                } else {
                    *(uint32_t*)(Ohi + (size_t)row * 512 + col) =
                        pack2(__float2half_rn(v0), __float2half_rn(v1));
                }
            }
        }
    }
    if (Wv) {
        int slot = blockIdx.y * 2 + wN;                // 0..7, distinct col bands
        #pragma unroll
        for (int mt = 0; mt < 2; mt++)
            #pragma unroll
            for (int half = 0; half < 2; half++) {
                float v = p[mt][half];
                v += __shfl_xor_sync(0xffffffffu, v, 1);
                v += __shfl_xor_sync(0xffffffffu, v, 2);
                if (tig == 0) {
                    int row = row0 + wM * 32 + mt * 16 + half * 8 + gid;
                    acc8[(size_t)row * 8 + slot] = v;
                }
            }
    }
}

// ---------------------------------------------------------------- chain: sum partials + b2 (+prev), emit tail / final
__global__ void chain_kernel(const float* __restrict__ acc8, const float* __restrict__ b2,
                             const float* __restrict__ prev, float* __restrict__ acc,
                             f16* __restrict__ thi,
                             float* __restrict__ fout) {
    int row = blockIdx.x * 256 + threadIdx.x;
    float s = __ldg(&b2[0]) + (prev ? prev[row] : 0.f);
    #pragma unroll
    for (int k = 0; k < 8; k++) s += acc8[(size_t)row * 8 + k];
    if (fout) { fout[row] = s; return; }
    acc[row] = s;
    uint4 zero = make_uint4(0, 0, 0, 0);
    uint4 first = make_uint4(pack2(__float2half_rn(s), __float2half_rn(0.f)), 0, 0, 0);
    uint4* th = (uint4*)(thi + (size_t)row * 64);
    th[0] = first;
    #pragma unroll
    for (int u = 1; u < 8; u++) th[u] = zero;
}

// ---------------------------------------------------------------- launch
extern "C" void kernel_launch(void* const* d_in, const int* in_sizes, int n_in,
                              void* d_out, int out_size) {
    const float* latent = (const float*)d_in[0];
    const float* pc     = (const float*)d_in[1];
    const float* W[3][3];
    const float* Bv[3][3];
    int p = 2;
    for (int s = 0; s < 3; s++)
        for (int j = 0; j < 3; j++) { W[s][j] = (const float*)d_in[p++]; Bv[s][j] = (const float*)d_in[p++]; }

    char* S = nullptr;
    cudaGetSymbolAddress((void**)&S, g_scratch);
    f16* Lhi  = (f16*)(S + OFF_L);
    f16* h0hi = (f16*)(S + OFF_H0);
    float* acc8 = (float*)(S + OFF_ACC8);
    f16* thi[3];
    for (int s = 0; s < 3; s++) thi[s] = (f16*)(S + OFF_T + s * TAILP);
    f16* w0[3], *w1[3];
    for (int s = 0; s < 3; s++) {
        w0[s] = (f16*)(S + OFF_W0 + s * W0P);
        w1[s] = (f16*)(S + OFF_W1 + s * W1P);
    }
    float* acc = (float*)(S + OFF_ACC);

    cudaFuncSetAttribute(gemm_kernel, cudaFuncAttributeMaxDynamicSharedMemorySize, GSMEM);

    int kdim0[3] = {FEATD + 12, FEATD + 1, FEATD + 1};
    dim3 ggrid(ROWSZ / 128, 512 / 128);

    // launch order: indices 3 and 4 are GEMMs so ncu (-s 5, +2 harness offset) captures one
    knn_kernel<<<BATCH * 8, 256>>>(pc, thi[0]);                                      // 0
    aconv_kernel<<<(ROWSZ * FEATD / 4) / 256, 256>>>(latent, Lhi);                   // 1
    {
        WJob j0 = {W[0][0], w0[0], kdim0[0], KPAD0};
        WJob j1 = {W[0][1], w1[0], 512, KPAD1};
        WJob j2 = {W[1][0], w0[1], kdim0[1], KPAD0};
        WJob j3 = {W[1][1], w1[1], 512, KPAD1};
        WJob j4 = {W[2][0], w0[2], kdim0[2], KPAD0};
        WJob j5 = {W[2][1], w1[2], 512, KPAD1};
        wconv_all<<<1536, 256>>>(j0, j1, j2, j3, j4, j5);                            // 2
    }

    for (int s = 0; s < 3; s++) {
        // layer 0: h0 = relu([latent, tail] W0 + b0)
        gemm_kernel<<<ggrid, 256, GSMEM>>>(Lhi, thi[s],
                                           w0[s], Bv[s][0],
                                           nullptr, h0hi,
                                           nullptr, nullptr, KPAD0, 9);
        // layer 1 fused with layer 2: partials of relu(h0 + h0 W1 + b1) . W2
        gemm_kernel<<<ggrid, 256, GSMEM>>>(h0hi, nullptr,
                                           w1[s], Bv[s][1],
                                           h0hi, nullptr,
                                           W[s][2], acc8, KPAD1, 8);
        const float* prev = (s == 0) ? nullptr : acc;
        chain_kernel<<<ROWSZ / 256, 256>>>(acc8, Bv[s][2], prev, acc,
                                           (s < 2) ? thi[s + 1] : nullptr,
                                           (s == 2) ? (float*)d_out : nullptr);
    }
}